// round 14
// baseline (speedup 1.0000x reference)
#include <cuda_runtime.h>
#include <cuda_fp16.h>
#include <cstddef>
#include <cstdint>

// Problem constants
#define NB   128          // batch
#define T    256          // sequence
#define CC   384          // embed
#define NH   6            // heads
#define HS   64           // head size
#define C4   1536         // 4*C
#define QKVN 1152         // 3*C
#define BT   32768        // NB*T

#define SCALE_ATT 0.05103103630798288f  // 384^-0.5

// ---------------- scratch (device globals; no allocation allowed) ----------
__device__ __half g_h[BT * CC];                      // LN output (fp16)
__device__ __half g_qkv[(size_t)BT * QKVN];          // q|k|v (fp16)
__device__ __half g_wei[(size_t)NB * NH * T * T];    // E^T[s][t] (fp16)
__device__ float  g_zpart[NB * NH * 4 * T];          // per-warp-column row sums
__device__ __half g_attn[BT * CC];                   // attention output (fp16)
__device__ __half g_x1[BT * CC];                     // residual stream (fp16)
__device__ __half g_u[(size_t)BT * C4];              // MLP hidden (fp16)
// n-major fp16 weights: Wt[n][k]
__device__ __half g_wqkvT[QKVN * CC];
__device__ __half g_wprojT[CC * CC];
__device__ __half g_w1T[(size_t)C4 * CC];
__device__ __half g_w2T[(size_t)CC * C4];

// ---------------- unified weight prep: all 4 transposes in one launch -------
__global__ void __launch_bounds__(256)
prep_all(const float* __restrict__ wq, const float* __restrict__ wk,
         const float* __restrict__ wv, const float* __restrict__ w_proj,
         const float* __restrict__ w1, const float* __restrict__ w2,
         __half* __restrict__ wqkvT, __half* __restrict__ wprojT,
         __half* __restrict__ w1T, __half* __restrict__ w2T) {
    __shared__ float tile[32][33];
    int bid = blockIdx.x;
    const float* src;
    __half* dst;
    int cols, dstLd, dstRowOff, tidx;
    if (bid < 432) {
        int j = bid / 24, t = bid % 24;
        int w = j / 6, h = j % 6;
        src = (w == 0 ? wq : w == 1 ? wk : wv) + (size_t)h * CC * HS;
        cols = HS; dst = wqkvT; dstLd = CC; dstRowOff = w * CC + h * HS;
        tidx = t;
    } else if (bid < 576) {
        src = w_proj; cols = CC; dst = wprojT; dstLd = CC; dstRowOff = 0;
        tidx = bid - 432;
    } else if (bid < 1152) {
        src = w1; cols = C4; dst = w1T; dstLd = CC; dstRowOff = 0;
        tidx = bid - 576;
    } else {
        src = w2; cols = CC; dst = w2T; dstLd = C4; dstRowOff = 0;
        tidx = bid - 1152;
    }
    int c32 = cols >> 5;
    int n0 = (tidx % c32) * 32;
    int k0 = (tidx / c32) * 32;
    int tx = threadIdx.x & 31, ty = threadIdx.x >> 5;
    #pragma unroll
    for (int i = 0; i < 32; i += 8)
        tile[ty + i][tx] = src[(size_t)(k0 + ty + i) * cols + n0 + tx];
    __syncthreads();
    #pragma unroll
    for (int i = 0; i < 32; i += 8)
        dst[(size_t)(dstRowOff + n0 + ty + i) * dstLd + k0 + tx] =
            __float2half(tile[tx][ty + i]);
}

// ---------------- LayerNorm: 2 rows per 256-thread block, fp16 out ----------
template <typename Tin>
__global__ void __launch_bounds__(256)
ln_kernel(const Tin* __restrict__ x, const float* __restrict__ g,
          const float* __restrict__ b, __half* __restrict__ out) {
    int half = threadIdx.x >> 7;          // 0 or 1
    int t = threadIdx.x & 127;
    int row = blockIdx.x * 2 + half;
    const Tin* xr = x + (size_t)row * CC;
    float v0 = (float)xr[t], v1 = (float)xr[t + 128], v2 = (float)xr[t + 256];
    float s  = v0 + v1 + v2;
    float ss = v0 * v0 + v1 * v1 + v2 * v2;
    __shared__ float red[2][4];
    __shared__ float red2[2][4];
    __shared__ float stat[2][2];
    #pragma unroll
    for (int o = 16; o > 0; o >>= 1) {
        s  += __shfl_down_sync(0xffffffffu, s, o);
        ss += __shfl_down_sync(0xffffffffu, ss, o);
    }
    int warp = t >> 5, lane = t & 31;
    if (lane == 0) { red[half][warp] = s; red2[half][warp] = ss; }
    __syncthreads();
    if (t == 0) {
        float S  = red[half][0] + red[half][1] + red[half][2] + red[half][3];
        float SS = red2[half][0] + red2[half][1] + red2[half][2] + red2[half][3];
        float mu = S * (1.0f / CC);
        float var = SS * (1.0f / CC) - mu * mu;
        stat[half][0] = mu;
        stat[half][1] = rsqrtf(var + 1e-5f);
    }
    __syncthreads();
    float mu = stat[half][0], inv = stat[half][1];
    __half* o = out + (size_t)row * CC;
    o[t]       = __float2half((v0 - mu) * inv * g[t]       + b[t]);
    o[t + 128] = __float2half((v1 - mu) * inv * g[t + 128] + b[t + 128]);
    o[t + 256] = __float2half((v2 - mu) * inv * g[t + 256] + b[t + 256]);
}

// ---------------- helpers -----------------------------------------------------
__device__ __forceinline__ uint32_t packh2(float lo, float hi) {
    __half2 h = __floats2half2_rn(lo, hi);
    return *(uint32_t*)&h;
}
__device__ __forceinline__ uint32_t smem_u32(const void* p) {
    uint32_t a;
    asm("{ .reg .u64 t; cvta.to.shared.u64 t, %1; cvt.u32.u64 %0, t; }"
        : "=r"(a) : "l"(p));
    return a;
}

__device__ __forceinline__ void mma_f16(float* d, const uint32_t* a, const uint32_t* b) {
    asm volatile(
        "mma.sync.aligned.m16n8k16.row.col.f32.f16.f16.f32 "
        "{%0,%1,%2,%3}, {%4,%5,%6,%7}, {%8,%9}, {%0,%1,%2,%3};"
        : "+f"(d[0]), "+f"(d[1]), "+f"(d[2]), "+f"(d[3])
        : "r"(a[0]), "r"(a[1]), "r"(a[2]), "r"(a[3]), "r"(b[0]), "r"(b[1]));
}

__device__ __forceinline__ void ldsm4t(uint32_t* r, uint32_t a) {
    asm volatile(
        "ldmatrix.sync.aligned.m8n8.x4.trans.shared.b16 {%0,%1,%2,%3}, [%4];"
        : "=r"(r[0]), "=r"(r[1]), "=r"(r[2]), "=r"(r[3]) : "r"(a));
}

// exp(x) for |x| <= ~1; degree-7 Taylor, pure FMA pipe.
__device__ __forceinline__ float exp_poly(float x) {
    float r = fmaf(x, 1.0f / 5040.0f, 1.0f / 720.0f);
    r = fmaf(x, r, 1.0f / 120.0f);
    r = fmaf(x, r, 1.0f / 24.0f);
    r = fmaf(x, r, 1.0f / 6.0f);
    r = fmaf(x, r, 0.5f);
    r = fmaf(x, r, 1.0f);
    r = fmaf(x, r, 1.0f);
    return r;
}

// ---------------- fp16 tensor-core GEMM, 3-stage cp.async --------------------
// EPI: 0 = plain, 1 = + bias + residual, 2 = relu(+ bias).
// OUTH: half output. RESH: residual operand is half.
template <int EPI, int OUTH, int RESH>
__global__ void __launch_bounds__(256, 2)
gemm_h(const __half* __restrict__ A, const __half* __restrict__ Bt,
       const float* __restrict__ bias, const void* __restrict__ res,
       void* __restrict__ CoutV, int M, int N, int K) {
    extern __shared__ char gsm[];
    uint32_t* Asm = (uint32_t*)gsm;                   // 3 * 2560 u32
    uint32_t* Bsm = (uint32_t*)(gsm + 3 * 10240);

    int tid  = threadIdx.x;
    int m0   = blockIdx.y * 128;
    int n0   = blockIdx.x * 128;
    int warp = tid >> 5, lane = tid & 31;
    int wm = (warp >> 1) * 32;
    int wn = (warp & 1) * 64;
    int qid  = lane >> 2;
    int qtid = lane & 3;

    float acc[2][8][4];
    #pragma unroll
    for (int i = 0; i < 2; i++)
        #pragma unroll
        for (int j = 0; j < 8; j++)
            #pragma unroll
            for (int q = 0; q < 4; q++) acc[i][j][q] = 0.0f;

    int row = tid >> 1;
    int gof = (tid & 1) * 16;
    int c2  = (tid & 1) * 8;

    const __half* Ap = A  + (size_t)(m0 + row) * K + gof;
    const __half* Bp = Bt + (size_t)(n0 + row) * K + gof;

    uint32_t sbase = smem_u32(gsm);
    uint32_t wordoff = (uint32_t)(row * 20 + c2) * 4u;
    uint32_t saA[3], saB[3];
    #pragma unroll
    for (int s = 0; s < 3; s++) {
        saA[s] = sbase + s * 10240u + wordoff;
        saB[s] = sbase + 30720u + s * 10240u + wordoff;
    }

    int KT = K >> 5;

    auto issue = [&](int kt, int buf) {
        const __half* pa = Ap + kt * 32;
        const __half* pb = Bp + kt * 32;
        asm volatile(
            "cp.async.cg.shared.global [%0], [%1], 16;\n\t"
            "cp.async.cg.shared.global [%2], [%3], 16;\n\t"
            "cp.async.cg.shared.global [%4], [%5], 16;\n\t"
            "cp.async.cg.shared.global [%6], [%7], 16;\n\t"
            "cp.async.commit_group;"
            :: "r"(saA[buf]), "l"(pa), "r"(saA[buf] + 16u), "l"(pa + 8),
               "r"(saB[buf]), "l"(pb), "r"(saB[buf] + 16u), "l"(pb + 8)
            : "memory");
    };

    issue(0, 0);
    issue(1, 1);

    int buf = 0;
    for (int kt = 0; kt < KT; kt++) {
        if (kt + 1 < KT)
            asm volatile("cp.async.wait_group 1;" ::: "memory");
        else
            asm volatile("cp.async.wait_group 0;" ::: "memory");
        __syncthreads();
        if (kt + 2 < KT) {
            int nb = buf + 2; if (nb >= 3) nb -= 3;
            issue(kt + 2, nb);
        }
        const uint32_t* As = Asm + buf * 2560;
        const uint32_t* Bs = Bsm + buf * 2560;
        #pragma unroll
        for (int ks = 0; ks < 2; ks++) {
            int kk = ks * 8;
            uint32_t af[2][4], bf[8][2];
            #pragma unroll
            for (int mt = 0; mt < 2; mt++) {
                int r = wm + mt * 16 + qid;
                af[mt][0] = As[r * 20 + kk + qtid];
                af[mt][1] = As[(r + 8) * 20 + kk + qtid];
                af[mt][2] = As[r * 20 + kk + qtid + 4];
                af[mt][3] = As[(r + 8) * 20 + kk + qtid + 4];
            }
            #pragma unroll
            for (int nt = 0; nt < 8; nt++) {
                int c = wn + nt * 8 + qid;
                bf[nt][0] = Bs[c * 20 + kk + qtid];
                bf[nt][1] = Bs[c * 20 + kk + qtid + 4];
            }
            #pragma unroll
            for (int mt = 0; mt < 2; mt++)
                #pragma unroll
                for (int nt = 0; nt < 8; nt++)
                    mma_f16(acc[mt][nt], af[mt], bf[nt]);
        }
        if (++buf == 3) buf = 0;
    }

    #pragma unroll
    for (int mt = 0; mt < 2; mt++) {
        #pragma unroll
        for (int nt = 0; nt < 8; nt++) {
            int r = m0 + wm + mt * 16 + qid;
            int c = n0 + wn + nt * 8 + 2 * qtid;
            #pragma unroll
            for (int half = 0; half < 2; half++) {
                int rr = r + half * 8;
                float2 v;
                v.x = acc[mt][nt][half * 2 + 0];
                v.y = acc[mt][nt][half * 2 + 1];
                if (EPI == 1) {
                    float2 bb = *(const float2*)(bias + c);
                    float2 rf;
                    if (RESH) {
                        uint32_t ru = *(const uint32_t*)((const __half*)res + (size_t)rr * N + c);
                        rf = __half22float2(*(__half2*)&ru);
                    } else {
                        rf = *(const float2*)((const float*)res + (size_t)rr * N + c);
                    }
                    v.x += bb.x + rf.x; v.y += bb.y + rf.y;
                } else if (EPI == 2) {
                    float2 bb = *(const float2*)(bias + c);
                    v.x = fmaxf(v.x + bb.x, 0.0f);
                    v.y = fmaxf(v.y + bb.y, 0.0f);
                }
                if (OUTH) {
                    __half* Co = (__half*)CoutV;
                    *(uint32_t*)(Co + (size_t)rr * N + c) = packh2(v.x, v.y);
                } else {
                    float* Co = (float*)CoutV;
                    *(float2*)(Co + (size_t)rr * N + c) = v;
                }
            }
        }
    }
}

// ---------------- scores: E^T[s][t] = mask ? exp(sigma*K[s].Q[t]) : 0 -------
// fp16 MMA; E staged through smem then written back with coalesced STG.128.
// smem: Ks[128][36]u32 + Qs[128][36]u32 + Est[128][136]h = 71680 B
__global__ void __launch_bounds__(256)
scores_tc(const __half* __restrict__ qkv, __half* __restrict__ wei,
          float* __restrict__ zpart) {
    extern __shared__ uint32_t ssm[];
    uint32_t* Ks = ssm;                // [128][36] half2
    uint32_t* Qs = ssm + 128 * 36;
    __half* Est = (__half*)(ssm + 2 * 128 * 36);   // [128][136]

    int bh = blockIdx.y;
    int b = bh / NH, h = bh % NH;
    int qidx = blockIdx.x;
    int sq = (qidx == 2) ? 1 : 0;
    int tq = (qidx == 0) ? 0 : 1;
    int s0 = sq * 128, t0 = tq * 128;
    int tid = threadIdx.x;

    #pragma unroll
    for (int i = 0; i < 4; i++) {
        int idx = tid + 256 * i;
        int r = idx >> 3, u4 = idx & 7;
        const __half* bk = qkv + (size_t)(b * T + s0 + r) * QKVN + CC + h * HS + u4 * 8;
        const __half* bq = qkv + (size_t)(b * T + t0 + r) * QKVN + h * HS + u4 * 8;
        *(uint4*)&Ks[r * 36 + u4 * 4] = *(const uint4*)bk;
        *(uint4*)&Qs[r * 36 + u4 * 4] = *(const uint4*)bq;
    }
    __syncthreads();

    int warp = tid >> 5, lane = tid & 31;
    int qid = lane >> 2, qtid = lane & 3;
    int wm = (warp >> 1) * 32;          // s offset in tile
    int wn = (warp & 1) * 64;           // t offset in tile

    float acc[2][8][4];
    #pragma unroll
    for (int i = 0; i < 2; i++)
        #pragma unroll
        for (int j = 0; j < 8; j++)
            #pragma unroll
            for (int q = 0; q < 4; q++) acc[i][j][q] = 0.0f;

    #pragma unroll
    for (int ks = 0; ks < 4; ks++) {
        int kk = ks * 8;
        uint32_t af[2][4], bf[8][2];
        #pragma unroll
        for (int mt = 0; mt < 2; mt++) {
            int r = wm + mt * 16 + qid;
            af[mt][0] = Ks[r * 36 + kk + qtid];
            af[mt][1] = Ks[(r + 8) * 36 + kk + qtid];
            af[mt][2] = Ks[r * 36 + kk + qtid + 4];
            af[mt][3] = Ks[(r + 8) * 36 + kk + qtid + 4];
        }
        #pragma unroll
        for (int nt = 0; nt < 8; nt++) {
            int c = wn + nt * 8 + qid;
            bf[nt][0] = Qs[c * 36 + kk + qtid];
            bf[nt][1] = Qs[c * 36 + kk + qtid + 4];
        }
        #pragma unroll
        for (int mt = 0; mt < 2; mt++)
            #pragma unroll
            for (int nt = 0; nt < 8; nt++)
                mma_f16(acc[mt][nt], af[mt], bf[nt]);
    }

    float rsum[2][2] = {{0.0f, 0.0f}, {0.0f, 0.0f}};

    // exp + mask + stage to smem (conflict-free: stride 136h = 4-bank rot/row)
    #pragma unroll
    for (int mt = 0; mt < 2; mt++)
        #pragma unroll
        for (int half = 0; half < 2; half++) {
            int sL = wm + mt * 16 + half * 8 + qid;     // local s row
            int s = s0 + sL;
            #pragma unroll
            for (int nt = 0; nt < 8; nt++) {
                int tL = wn + nt * 8 + 2 * qtid;
                int tb = t0 + tL;
                float e0 = 0.0f, e1 = 0.0f;
                if (tb + 0 >= s) e0 = exp_poly(acc[mt][nt][half * 2 + 0] * SCALE_ATT);
                if (tb + 1 >= s) e1 = exp_poly(acc[mt][nt][half * 2 + 1] * SCALE_ATT);
                rsum[mt][half] += e0 + e1;
                *(uint32_t*)&Est[sL * 136 + tL] = packh2(e0, e1);
            }
        }
    __syncthreads();

    // coalesced writeback: 128 rows x 16 uint4 segs = 2048 uint4, 8 per thread
    __half* W = wei + (size_t)bh * (T * T);
    #pragma unroll
    for (int j = 0; j < 8; j++) {
        int lin = tid + 256 * j;
        int r = lin >> 4, seg = lin & 15;
        *(uint4*)(W + (size_t)(s0 + r) * T + t0 + seg * 8) =
            *(const uint4*)&Est[r * 136 + seg * 8];
    }

    int tcol = tq * 2 + (warp & 1);
    #pragma unroll
    for (int mt = 0; mt < 2; mt++)
        #pragma unroll
        for (int half = 0; half < 2; half++) {
            float v = rsum[mt][half];
            v += __shfl_xor_sync(0xffffffffu, v, 1);
            v += __shfl_xor_sync(0xffffffffu, v, 2);
            if (qtid == 0) {
                int s = s0 + wm + mt * 16 + half * 8 + qid;
                zpart[(bh * 4 + tcol) * T + s] = v;
            }
        }
}

// ---------------- av: O[t][d] = sum_s E^T[s][t] * (iz[s]*V[s][d]) -----------
#define ES_STR 136
#define VS_STR 72
__global__ void __launch_bounds__(256)
av_tc(const __half* __restrict__ qkv, const __half* __restrict__ wei,
      const float* __restrict__ zp, __half* __restrict__ attn) {
    extern __shared__ char avsm[];
    __half* Vs = (__half*)(avsm + 2 * 32 * ES_STR * 2);
    float* izs = (float*)(avsm + 2 * 32 * ES_STR * 2 + 2 * 32 * VS_STR * 2);

    int bh = blockIdx.y;
    int b = bh / NH, h = bh % NH;
    int t0 = blockIdx.x * 128;
    int tid = threadIdx.x;
    int lane = tid & 31, warp = tid >> 5;

    {
        const float* p = zp + bh * 4 * T;
        int s = tid;
        float z = p[2 * T + s] + p[3 * T + s];
        if (s < 128) z += p[s] + p[T + s];
        izs[s] = 1.0f / z;
    }
    __syncthreads();

    const __half* W  = wei + (size_t)bh * (T * T);
    const __half* Vg = qkv + (size_t)(b * T) * QKVN + 2 * CC + h * HS;
    int nchunk = (t0 == 0) ? 4 : 8;

    uint32_t esb = smem_u32(avsm);
    uint32_t vsb = smem_u32(Vs);

    int vr = tid >> 3, vdc = (tid & 7) * 8;

    auto issueE = [&](int ch, int buf) {
        #pragma unroll
        for (int i = 0; i < 2; i++) {
            int idx = tid + 256 * i;
            int r = idx >> 4, seg = idx & 15;
            uint32_t dst = esb + (uint32_t)(buf * 32 * ES_STR * 2 + r * ES_STR * 2 + seg * 16);
            const __half* src = W + (size_t)(ch * 32 + r) * T + t0 + seg * 8;
            asm volatile("cp.async.cg.shared.global [%0], [%1], 16;"
                         :: "r"(dst), "l"(src) : "memory");
        }
        asm volatile("cp.async.commit_group;" ::: "memory");
    };
    uint4 vreg;
    float izr;
    auto fetchV = [&](int ch) {
        vreg = *(const uint4*)(Vg + (size_t)(ch * 32 + vr) * QKVN + vdc);
        izr = izs[ch * 32 + vr];
    };
    auto stageV = [&](int buf) {
        __half2 hiz = __float2half2_rn(izr);
        __half2* hv = (__half2*)&vreg;
        uint4 o;
        __half2* ho = (__half2*)&o;
        ho[0] = __hmul2(hv[0], hiz);
        ho[1] = __hmul2(hv[1], hiz);
        ho[2] = __hmul2(hv[2], hiz);
        ho[3] = __hmul2(hv[3], hiz);
        *(uint4*)(Vs + buf * 32 * VS_STR + vr * VS_STR + vdc) = o;
    };

    int wm = (warp >> 1) * 32;
    int wn = (warp & 1) * 32;
    int grp = lane >> 3, lr = lane & 7;
    int qid = lane >> 2, qtid = lane & 3;

    float acc[2][4][4];
    #pragma unroll
    for (int i = 0; i < 2; i++)
        #pragma unroll
        for (int j = 0; j < 4; j++)
            #pragma unroll
            for (int q = 0; q < 4; q++) acc[i][j][q] = 0.0f;

    fetchV(0);
    issueE(0, 0);
    stageV(0);
    asm volatile("cp.async.wait_group 0;" ::: "memory");
    __syncthreads();

    int buf = 0;
    for (int ch = 0; ch < nchunk; ch++) {
        if (ch + 1 < nchunk) {
            fetchV(ch + 1);
            issueE(ch + 1, buf ^ 1);
        }
        uint32_t eB = esb + (uint32_t)(buf * 32 * ES_STR * 2);
        uint32_t vB = vsb + (uint32_t)(buf * 32 * VS_STR * 2);
        #pragma unroll
        for (int ks = 0; ks < 2; ks++) {
            int kk = ks * 16;
            uint32_t af[2][4];
            #pragma unroll
            for (int mt = 0; mt < 2; mt++) {
                int tb = wm + mt * 16;
                int srow = kk + (grp >> 1) * 8 + lr;
                int tcol = tb + (grp & 1) * 8;
                ldsm4t(af[mt], eB + (uint32_t)(srow * ES_STR + tcol) * 2u);
            }
            uint32_t bf[4][2];
            #pragma unroll
            for (int ntp = 0; ntp < 2; ntp++) {
                int db = wn + ntp * 16;
                int srow = kk + (grp & 1) * 8 + lr;
                int dcol = db + (grp >> 1) * 8;
                uint32_t r4[4];
                ldsm4t(r4, vB + (uint32_t)(srow * VS_STR + dcol) * 2u);
                bf[2 * ntp][0] = r4[0]; bf[2 * ntp][1] = r4[1];
                bf[2 * ntp + 1][0] = r4[2]; bf[2 * ntp + 1][1] = r4[3];
            }
            #pragma unroll
            for (int mt = 0; mt < 2; mt++)
                #pragma unroll
                for (int nt = 0; nt < 4; nt++)
                    mma_f16(acc[mt][nt], af[mt], bf[nt]);
        }
        if (ch + 1 < nchunk) {
            stageV(buf ^ 1);
            asm volatile("cp.async.wait_group 0;" ::: "memory");
            __syncthreads();
            buf ^= 1;
        }
    }

    #pragma unroll
    for (int mt = 0; mt < 2; mt++)
        #pragma unroll
        for (int nt = 0; nt < 4; nt++)
            #pragma unroll
            for (int half = 0; half < 2; half++) {
                int t = t0 + wm + mt * 16 + half * 8 + qid;
                int d = wn + nt * 8 + 2 * qtid;
                *(uint32_t*)(attn + (size_t)(b * T + t) * CC + h * HS + d) =
                    packh2(acc[mt][nt][half * 2 + 0], acc[mt][nt][half * 2 + 1]);
            }
}

// ---------------- launch ----------------------------------------------------
extern "C" void kernel_launch(void* const* d_in, const int* in_sizes, int n_in,
                              void* d_out, int out_size) {
    (void)in_sizes; (void)n_in; (void)out_size;
    const float* x      = (const float*)d_in[0];
    const float* wq     = (const float*)d_in[1];
    const float* wk     = (const float*)d_in[2];
    const float* wv     = (const float*)d_in[3];
    const float* w_proj = (const float*)d_in[4];
    const float* b_proj = (const float*)d_in[5];
    const float* w1     = (const float*)d_in[6];
    const float* b1     = (const float*)d_in[7];
    const float* w2     = (const float*)d_in[8];
    const float* b2     = (const float*)d_in[9];
    const float* ln1_g  = (const float*)d_in[10];
    const float* ln1_b  = (const float*)d_in[11];
    const float* ln2_g  = (const float*)d_in[12];
    const float* ln2_b  = (const float*)d_in[13];
    float* out = (float*)d_out;

    void *ph, *pqkv, *pwei, *pzp, *pattn, *px1, *pu;
    void *pwqkv, *pwproj, *pw1, *pw2;
    cudaGetSymbolAddress(&ph,    g_h);
    cudaGetSymbolAddress(&pqkv,  g_qkv);
    cudaGetSymbolAddress(&pwei,  g_wei);
    cudaGetSymbolAddress(&pzp,   g_zpart);
    cudaGetSymbolAddress(&pattn, g_attn);
    cudaGetSymbolAddress(&px1,   g_x1);
    cudaGetSymbolAddress(&pu,    g_u);
    cudaGetSymbolAddress(&pwqkv, g_wqkvT);
    cudaGetSymbolAddress(&pwproj, g_wprojT);
    cudaGetSymbolAddress(&pw1,   g_w1T);
    cudaGetSymbolAddress(&pw2,   g_w2T);
    __half* fh     = (__half*)ph;
    __half* fqkv   = (__half*)pqkv;
    __half* fwei   = (__half*)pwei;
    float*  fzp    = (float*)pzp;
    __half* fattn  = (__half*)pattn;
    __half* fx1    = (__half*)px1;
    __half* fu     = (__half*)pu;
    __half* fwqkvT = (__half*)pwqkv;
    __half* fwprojT= (__half*)pwproj;
    __half* fw1T   = (__half*)pw1;
    __half* fw2T   = (__half*)pw2;

    const int SMEM_S  = 2 * 128 * 36 * 4 + 128 * 136 * 2;            // 71680
    const int SMEM_AV = 2 * 32 * ES_STR * 2 + 2 * 32 * VS_STR * 2 + 1024; // 27648
    const int SMEM_G  = 6 * 10240;                                   // 61440
    cudaFuncSetAttribute(scores_tc, cudaFuncAttributeMaxDynamicSharedMemorySize, SMEM_S);
    cudaFuncSetAttribute(av_tc, cudaFuncAttributeMaxDynamicSharedMemorySize, SMEM_AV);
    cudaFuncSetAttribute(gemm_h<0, 1, 0>, cudaFuncAttributeMaxDynamicSharedMemorySize, SMEM_G);
    cudaFuncSetAttribute(gemm_h<1, 1, 0>, cudaFuncAttributeMaxDynamicSharedMemorySize, SMEM_G);
    cudaFuncSetAttribute(gemm_h<1, 0, 1>, cudaFuncAttributeMaxDynamicSharedMemorySize, SMEM_G);
    cudaFuncSetAttribute(gemm_h<2, 1, 0>, cudaFuncAttributeMaxDynamicSharedMemorySize, SMEM_G);

    // 0) weight prep (fp16, n-major) — single launch
    prep_all<<<1728, 256>>>(wq, wk, wv, w_proj, w1, w2,
                            fwqkvT, fwprojT, fw1T, fw2T);
    // 1) LN1 (fp32 in), 2 rows per block
    ln_kernel<float><<<BT / 2, 256>>>(x, ln1_g, ln1_b, fh);
    // 2) QKV projection (out fp16)
    gemm_h<0, 1, 0><<<dim3(QKVN / 128, BT / 128), 256, SMEM_G>>>(
        fh, fwqkvT, nullptr, nullptr, fqkv, BT, QKVN, CC);
    // 3) scores -> E = exp(sigma*S) masked (fp16), + row-sum partials
    scores_tc<<<dim3(3, NB * NH), 256, SMEM_S>>>(fqkv, fwei, fzp);
    // 4) O = E * (iz*V)  (fp16 out; iz computed in-kernel from zpart)
    av_tc<<<dim3(2, NB * NH), 256, SMEM_AV>>>(fqkv, fwei, fzp, fattn);
    // 5) x1 = x + attn @ w_proj + b_proj (fp16 out, fp32 residual)
    gemm_h<1, 1, 0><<<dim3(CC / 128, BT / 128), 256, SMEM_G>>>(
        fattn, fwprojT, b_proj, x, fx1, BT, CC, CC);
    // 6) LN2 (fp16 in), 2 rows per block
    ln_kernel<__half><<<BT / 2, 256>>>(fx1, ln2_g, ln2_b, fh);
    // 7) u = relu(h2 @ w1 + b1) (fp16 out)
    gemm_h<2, 1, 0><<<dim3(C4 / 128, BT / 128), 256, SMEM_G>>>(
        fh, fw1T, b1, nullptr, fu, BT, C4, CC);
    // 8) out = x1 + u @ w2 + b2 (fp32 out, fp16 residual)
    gemm_h<1, 0, 1><<<dim3(CC / 128, BT / 128), 256, SMEM_G>>>(
        fu, fw2T, b2, fx1, out, BT, CC, C4);
}

// round 15
// speedup vs baseline: 1.2298x; 1.2298x over previous
#include <cuda_runtime.h>
#include <cuda_fp16.h>
#include <cstddef>
#include <cstdint>

// Problem constants
#define NB   128          // batch
#define T    256          // sequence
#define CC   384          // embed
#define NH   6            // heads
#define HS   64           // head size
#define C4   1536         // 4*C
#define QKVN 1152         // 3*C
#define BT   32768        // NB*T

#define SCALE_ATT 0.05103103630798288f  // 384^-0.5

// ---------------- scratch (device globals; no allocation allowed) ----------
__device__ __half g_h[BT * CC];                      // LN output (fp16)
__device__ __half g_qkv[(size_t)BT * QKVN];          // q|k|v (fp16)
__device__ __half g_wei[(size_t)NB * NH * T * T];    // E^T[s][t] (fp16)
__device__ float  g_zpart[NB * NH * 4 * T];          // per-warp-column row sums
__device__ __half g_attn[BT * CC];                   // attention output (fp16)
__device__ __half g_x1[BT * CC];                     // residual stream (fp16)
__device__ __half g_u[(size_t)BT * C4];              // MLP hidden (fp16)
// n-major fp16 weights: Wt[n][k]
__device__ __half g_wqkvT[QKVN * CC];
__device__ __half g_wprojT[CC * CC];
__device__ __half g_w1T[(size_t)C4 * CC];
__device__ __half g_w2T[(size_t)CC * C4];

// ---------------- unified weight prep: all 4 transposes in one launch -------
__global__ void __launch_bounds__(256)
prep_all(const float* __restrict__ wq, const float* __restrict__ wk,
         const float* __restrict__ wv, const float* __restrict__ w_proj,
         const float* __restrict__ w1, const float* __restrict__ w2,
         __half* __restrict__ wqkvT, __half* __restrict__ wprojT,
         __half* __restrict__ w1T, __half* __restrict__ w2T) {
    __shared__ float tile[32][33];
    int bid = blockIdx.x;
    const float* src;
    __half* dst;
    int cols, dstLd, dstRowOff, tidx;
    if (bid < 432) {
        int j = bid / 24, t = bid % 24;
        int w = j / 6, h = j % 6;
        src = (w == 0 ? wq : w == 1 ? wk : wv) + (size_t)h * CC * HS;
        cols = HS; dst = wqkvT; dstLd = CC; dstRowOff = w * CC + h * HS;
        tidx = t;
    } else if (bid < 576) {
        src = w_proj; cols = CC; dst = wprojT; dstLd = CC; dstRowOff = 0;
        tidx = bid - 432;
    } else if (bid < 1152) {
        src = w1; cols = C4; dst = w1T; dstLd = CC; dstRowOff = 0;
        tidx = bid - 576;
    } else {
        src = w2; cols = CC; dst = w2T; dstLd = C4; dstRowOff = 0;
        tidx = bid - 1152;
    }
    int c32 = cols >> 5;
    int n0 = (tidx % c32) * 32;
    int k0 = (tidx / c32) * 32;
    int tx = threadIdx.x & 31, ty = threadIdx.x >> 5;
    #pragma unroll
    for (int i = 0; i < 32; i += 8)
        tile[ty + i][tx] = src[(size_t)(k0 + ty + i) * cols + n0 + tx];
    __syncthreads();
    #pragma unroll
    for (int i = 0; i < 32; i += 8)
        dst[(size_t)(dstRowOff + n0 + ty + i) * dstLd + k0 + tx] =
            __float2half(tile[tx][ty + i]);
}

// ---------------- LayerNorm: 2 rows per 256-thread block, fp16 out ----------
template <typename Tin>
__global__ void __launch_bounds__(256)
ln_kernel(const Tin* __restrict__ x, const float* __restrict__ g,
          const float* __restrict__ b, __half* __restrict__ out) {
    int half = threadIdx.x >> 7;          // 0 or 1
    int t = threadIdx.x & 127;
    int row = blockIdx.x * 2 + half;
    const Tin* xr = x + (size_t)row * CC;
    float v0 = (float)xr[t], v1 = (float)xr[t + 128], v2 = (float)xr[t + 256];
    float s  = v0 + v1 + v2;
    float ss = v0 * v0 + v1 * v1 + v2 * v2;
    __shared__ float red[2][4];
    __shared__ float red2[2][4];
    __shared__ float stat[2][2];
    #pragma unroll
    for (int o = 16; o > 0; o >>= 1) {
        s  += __shfl_down_sync(0xffffffffu, s, o);
        ss += __shfl_down_sync(0xffffffffu, ss, o);
    }
    int warp = t >> 5, lane = t & 31;
    if (lane == 0) { red[half][warp] = s; red2[half][warp] = ss; }
    __syncthreads();
    if (t == 0) {
        float S  = red[half][0] + red[half][1] + red[half][2] + red[half][3];
        float SS = red2[half][0] + red2[half][1] + red2[half][2] + red2[half][3];
        float mu = S * (1.0f / CC);
        float var = SS * (1.0f / CC) - mu * mu;
        stat[half][0] = mu;
        stat[half][1] = rsqrtf(var + 1e-5f);
    }
    __syncthreads();
    float mu = stat[half][0], inv = stat[half][1];
    __half* o = out + (size_t)row * CC;
    o[t]       = __float2half((v0 - mu) * inv * g[t]       + b[t]);
    o[t + 128] = __float2half((v1 - mu) * inv * g[t + 128] + b[t + 128]);
    o[t + 256] = __float2half((v2 - mu) * inv * g[t + 256] + b[t + 256]);
}

// ---------------- helpers -----------------------------------------------------
__device__ __forceinline__ uint32_t packh2(float lo, float hi) {
    __half2 h = __floats2half2_rn(lo, hi);
    return *(uint32_t*)&h;
}
__device__ __forceinline__ uint32_t smem_u32(const void* p) {
    uint32_t a;
    asm("{ .reg .u64 t; cvta.to.shared.u64 t, %1; cvt.u32.u64 %0, t; }"
        : "=r"(a) : "l"(p));
    return a;
}

__device__ __forceinline__ void mma_f16(float* d, const uint32_t* a, const uint32_t* b) {
    asm volatile(
        "mma.sync.aligned.m16n8k16.row.col.f32.f16.f16.f32 "
        "{%0,%1,%2,%3}, {%4,%5,%6,%7}, {%8,%9}, {%0,%1,%2,%3};"
        : "+f"(d[0]), "+f"(d[1]), "+f"(d[2]), "+f"(d[3])
        : "r"(a[0]), "r"(a[1]), "r"(a[2]), "r"(a[3]), "r"(b[0]), "r"(b[1]));
}

__device__ __forceinline__ void ldsm4t(uint32_t* r, uint32_t a) {
    asm volatile(
        "ldmatrix.sync.aligned.m8n8.x4.trans.shared.b16 {%0,%1,%2,%3}, [%4];"
        : "=r"(r[0]), "=r"(r[1]), "=r"(r[2]), "=r"(r[3]) : "r"(a));
}

// exp(x) for |x| <= ~1; degree-7 Taylor, pure FMA pipe.
__device__ __forceinline__ float exp_poly(float x) {
    float r = fmaf(x, 1.0f / 5040.0f, 1.0f / 720.0f);
    r = fmaf(x, r, 1.0f / 120.0f);
    r = fmaf(x, r, 1.0f / 24.0f);
    r = fmaf(x, r, 1.0f / 6.0f);
    r = fmaf(x, r, 0.5f);
    r = fmaf(x, r, 1.0f);
    r = fmaf(x, r, 1.0f);
    return r;
}

// ---------------- fp16 tensor-core GEMM, BK=64, 3-stage cp.async -------------
// C = epi(A(MxK row, half) * Bt(NxK row, half)^T); 128x128 tile, BK=64 halves.
// EPI: 0 = plain, 1 = + bias + residual, 2 = relu(+ bias).
// OUTH: half output. RESH: residual operand is half.
// smem: 3 stages x (A[128][36]u32 + B[128][36]u32) = 110592 B
#define GS_STR 36                     // u32 stride per row (64 halves + pad)
#define GS_TILE (128 * GS_STR)        // u32 per matrix per stage (4608)
#define GS_STAGE (2 * GS_TILE)        // u32 per stage (A+B)
template <int EPI, int OUTH, int RESH>
__global__ void __launch_bounds__(256, 2)
gemm_h(const __half* __restrict__ A, const __half* __restrict__ Bt,
       const float* __restrict__ bias, const void* __restrict__ res,
       void* __restrict__ CoutV, int M, int N, int K) {
    extern __shared__ char gsm[];
    uint32_t* Ssm = (uint32_t*)gsm;

    int tid  = threadIdx.x;
    int m0   = blockIdx.y * 128;
    int n0   = blockIdx.x * 128;
    int warp = tid >> 5, lane = tid & 31;
    int wm = (warp >> 1) * 32;
    int wn = (warp & 1) * 64;
    int qid  = lane >> 2;
    int qtid = lane & 3;

    float acc[2][8][4];
    #pragma unroll
    for (int i = 0; i < 2; i++)
        #pragma unroll
        for (int j = 0; j < 8; j++)
            #pragma unroll
            for (int q = 0; q < 4; q++) acc[i][j][q] = 0.0f;

    // copy assignment: 128 rows x 8 segs (16B) per matrix = 1024 segs; 4/thread
    uint32_t sbase = smem_u32(gsm);
    int KT = K >> 6;

    auto issue = [&](int kt, int buf) {
        uint32_t stg = sbase + (uint32_t)(buf * GS_STAGE) * 4u;
        #pragma unroll
        for (int i = 0; i < 4; i++) {
            int idx = tid + 256 * i;
            int r = idx >> 3, seg = idx & 7;
            uint32_t da = stg + (uint32_t)(r * GS_STR * 4 + seg * 16);
            uint32_t db = da + (uint32_t)(GS_TILE * 4);
            const __half* pa = A  + (size_t)(m0 + r) * K + kt * 64 + seg * 8;
            const __half* pb = Bt + (size_t)(n0 + r) * K + kt * 64 + seg * 8;
            asm volatile(
                "cp.async.cg.shared.global [%0], [%1], 16;\n\t"
                "cp.async.cg.shared.global [%2], [%3], 16;"
                :: "r"(da), "l"(pa), "r"(db), "l"(pb) : "memory");
        }
        asm volatile("cp.async.commit_group;" ::: "memory");
    };

    issue(0, 0);
    if (KT > 1) issue(1, 1);

    int buf = 0;
    for (int kt = 0; kt < KT; kt++) {
        if (kt + 1 < KT)
            asm volatile("cp.async.wait_group 1;" ::: "memory");
        else
            asm volatile("cp.async.wait_group 0;" ::: "memory");
        __syncthreads();
        if (kt + 2 < KT) {
            int nb = buf + 2; if (nb >= 3) nb -= 3;
            issue(kt + 2, nb);
        }
        const uint32_t* As = Ssm + buf * GS_STAGE;
        const uint32_t* Bs = As + GS_TILE;
        #pragma unroll
        for (int ks = 0; ks < 4; ks++) {
            int kk = ks * 8;                    // half2 units
            uint32_t af[2][4], bf[8][2];
            #pragma unroll
            for (int mt = 0; mt < 2; mt++) {
                int r = wm + mt * 16 + qid;
                af[mt][0] = As[r * GS_STR + kk + qtid];
                af[mt][1] = As[(r + 8) * GS_STR + kk + qtid];
                af[mt][2] = As[r * GS_STR + kk + qtid + 4];
                af[mt][3] = As[(r + 8) * GS_STR + kk + qtid + 4];
            }
            #pragma unroll
            for (int nt = 0; nt < 8; nt++) {
                int c = wn + nt * 8 + qid;
                bf[nt][0] = Bs[c * GS_STR + kk + qtid];
                bf[nt][1] = Bs[c * GS_STR + kk + qtid + 4];
            }
            #pragma unroll
            for (int mt = 0; mt < 2; mt++)
                #pragma unroll
                for (int nt = 0; nt < 8; nt++)
                    mma_f16(acc[mt][nt], af[mt], bf[nt]);
        }
        if (++buf == 3) buf = 0;
    }

    #pragma unroll
    for (int mt = 0; mt < 2; mt++) {
        #pragma unroll
        for (int nt = 0; nt < 8; nt++) {
            int r = m0 + wm + mt * 16 + qid;
            int c = n0 + wn + nt * 8 + 2 * qtid;
            #pragma unroll
            for (int half = 0; half < 2; half++) {
                int rr = r + half * 8;
                float2 v;
                v.x = acc[mt][nt][half * 2 + 0];
                v.y = acc[mt][nt][half * 2 + 1];
                if (EPI == 1) {
                    float2 bb = *(const float2*)(bias + c);
                    float2 rf;
                    if (RESH) {
                        uint32_t ru = *(const uint32_t*)((const __half*)res + (size_t)rr * N + c);
                        rf = __half22float2(*(__half2*)&ru);
                    } else {
                        rf = *(const float2*)((const float*)res + (size_t)rr * N + c);
                    }
                    v.x += bb.x + rf.x; v.y += bb.y + rf.y;
                } else if (EPI == 2) {
                    float2 bb = *(const float2*)(bias + c);
                    v.x = fmaxf(v.x + bb.x, 0.0f);
                    v.y = fmaxf(v.y + bb.y, 0.0f);
                }
                if (OUTH) {
                    __half* Co = (__half*)CoutV;
                    *(uint32_t*)(Co + (size_t)rr * N + c) = packh2(v.x, v.y);
                } else {
                    float* Co = (float*)CoutV;
                    *(float2*)(Co + (size_t)rr * N + c) = v;
                }
            }
        }
    }
}

// ---------------- scores: E^T[s][t] = mask ? exp(sigma*K[s].Q[t]) : 0 -------
// fp16 MMA; qkv fp16; E fp16; per-warp-column row-sum partials in fp32.
__global__ void __launch_bounds__(256)
scores_tc(const __half* __restrict__ qkv, __half* __restrict__ wei,
          float* __restrict__ zpart) {
    extern __shared__ uint32_t ssm[];
    uint32_t* Ks = ssm;                // [128][36] half2
    uint32_t* Qs = ssm + 128 * 36;

    int bh = blockIdx.y;
    int b = bh / NH, h = bh % NH;
    int qidx = blockIdx.x;
    int sq = (qidx == 2) ? 1 : 0;
    int tq = (qidx == 0) ? 0 : 1;
    int s0 = sq * 128, t0 = tq * 128;
    int tid = threadIdx.x;

    #pragma unroll
    for (int i = 0; i < 4; i++) {
        int idx = tid + 256 * i;
        int r = idx >> 3, u4 = idx & 7;
        const __half* bk = qkv + (size_t)(b * T + s0 + r) * QKVN + CC + h * HS + u4 * 8;
        const __half* bq = qkv + (size_t)(b * T + t0 + r) * QKVN + h * HS + u4 * 8;
        *(uint4*)&Ks[r * 36 + u4 * 4] = *(const uint4*)bk;
        *(uint4*)&Qs[r * 36 + u4 * 4] = *(const uint4*)bq;
    }
    __syncthreads();

    int warp = tid >> 5, lane = tid & 31;
    int qid = lane >> 2, qtid = lane & 3;
    int wm = (warp >> 1) * 32;          // s offset in tile
    int wn = (warp & 1) * 64;           // t offset in tile

    float acc[2][8][4];
    #pragma unroll
    for (int i = 0; i < 2; i++)
        #pragma unroll
        for (int j = 0; j < 8; j++)
            #pragma unroll
            for (int q = 0; q < 4; q++) acc[i][j][q] = 0.0f;

    #pragma unroll
    for (int ks = 0; ks < 4; ks++) {
        int kk = ks * 8;
        uint32_t af[2][4], bf[8][2];
        #pragma unroll
        for (int mt = 0; mt < 2; mt++) {
            int r = wm + mt * 16 + qid;
            af[mt][0] = Ks[r * 36 + kk + qtid];
            af[mt][1] = Ks[(r + 8) * 36 + kk + qtid];
            af[mt][2] = Ks[r * 36 + kk + qtid + 4];
            af[mt][3] = Ks[(r + 8) * 36 + kk + qtid + 4];
        }
        #pragma unroll
        for (int nt = 0; nt < 8; nt++) {
            int c = wn + nt * 8 + qid;
            bf[nt][0] = Qs[c * 36 + kk + qtid];
            bf[nt][1] = Qs[c * 36 + kk + qtid + 4];
        }
        #pragma unroll
        for (int mt = 0; mt < 2; mt++)
            #pragma unroll
            for (int nt = 0; nt < 8; nt++)
                mma_f16(acc[mt][nt], af[mt], bf[nt]);
    }

    __half* W = wei + (size_t)bh * (T * T);
    float rsum[2][2] = {{0.0f, 0.0f}, {0.0f, 0.0f}};

    #pragma unroll
    for (int mt = 0; mt < 2; mt++)
        #pragma unroll
        for (int half = 0; half < 2; half++) {
            int s = s0 + wm + mt * 16 + half * 8 + qid;
            #pragma unroll
            for (int nt = 0; nt < 8; nt++) {
                int tb = t0 + wn + nt * 8 + 2 * qtid;
                float e0 = 0.0f, e1 = 0.0f;
                if (tb + 0 >= s) e0 = exp_poly(acc[mt][nt][half * 2 + 0] * SCALE_ATT);
                if (tb + 1 >= s) e1 = exp_poly(acc[mt][nt][half * 2 + 1] * SCALE_ATT);
                rsum[mt][half] += e0 + e1;
                *(uint32_t*)(W + (size_t)s * T + tb) = packh2(e0, e1);
            }
        }

    int tcol = tq * 2 + (warp & 1);
    #pragma unroll
    for (int mt = 0; mt < 2; mt++)
        #pragma unroll
        for (int half = 0; half < 2; half++) {
            float v = rsum[mt][half];
            v += __shfl_xor_sync(0xffffffffu, v, 1);
            v += __shfl_xor_sync(0xffffffffu, v, 2);
            if (qtid == 0) {
                int s = s0 + wm + mt * 16 + half * 8 + qid;
                zpart[(bh * 4 + tcol) * T + s] = v;
            }
        }
}

// ---------------- av: O[t][d] = sum_s E^T[s][t] * (iz[s]*V[s][d]) -----------
#define ES_STR 136
#define VS_STR 72
__global__ void __launch_bounds__(256)
av_tc(const __half* __restrict__ qkv, const __half* __restrict__ wei,
      const float* __restrict__ zp, __half* __restrict__ attn) {
    extern __shared__ char avsm[];
    __half* Vs = (__half*)(avsm + 2 * 32 * ES_STR * 2);
    float* izs = (float*)(avsm + 2 * 32 * ES_STR * 2 + 2 * 32 * VS_STR * 2);

    int bh = blockIdx.y;
    int b = bh / NH, h = bh % NH;
    int t0 = blockIdx.x * 128;
    int tid = threadIdx.x;
    int lane = tid & 31, warp = tid >> 5;

    {
        const float* p = zp + bh * 4 * T;
        int s = tid;
        float z = p[2 * T + s] + p[3 * T + s];
        if (s < 128) z += p[s] + p[T + s];
        izs[s] = 1.0f / z;
    }
    __syncthreads();

    const __half* W  = wei + (size_t)bh * (T * T);
    const __half* Vg = qkv + (size_t)(b * T) * QKVN + 2 * CC + h * HS;
    int nchunk = (t0 == 0) ? 4 : 8;

    uint32_t esb = smem_u32(avsm);
    uint32_t vsb = smem_u32(Vs);

    int vr = tid >> 3, vdc = (tid & 7) * 8;

    auto issueE = [&](int ch, int buf) {
        #pragma unroll
        for (int i = 0; i < 2; i++) {
            int idx = tid + 256 * i;
            int r = idx >> 4, seg = idx & 15;
            uint32_t dst = esb + (uint32_t)(buf * 32 * ES_STR * 2 + r * ES_STR * 2 + seg * 16);
            const __half* src = W + (size_t)(ch * 32 + r) * T + t0 + seg * 8;
            asm volatile("cp.async.cg.shared.global [%0], [%1], 16;"
                         :: "r"(dst), "l"(src) : "memory");
        }
        asm volatile("cp.async.commit_group;" ::: "memory");
    };
    uint4 vreg;
    float izr;
    auto fetchV = [&](int ch) {
        vreg = *(const uint4*)(Vg + (size_t)(ch * 32 + vr) * QKVN + vdc);
        izr = izs[ch * 32 + vr];
    };
    auto stageV = [&](int buf) {
        __half2 hiz = __float2half2_rn(izr);
        __half2* hv = (__half2*)&vreg;
        uint4 o;
        __half2* ho = (__half2*)&o;
        ho[0] = __hmul2(hv[0], hiz);
        ho[1] = __hmul2(hv[1], hiz);
        ho[2] = __hmul2(hv[2], hiz);
        ho[3] = __hmul2(hv[3], hiz);
        *(uint4*)(Vs + buf * 32 * VS_STR + vr * VS_STR + vdc) = o;
    };

    int wm = (warp >> 1) * 32;
    int wn = (warp & 1) * 32;
    int grp = lane >> 3, lr = lane & 7;
    int qid = lane >> 2, qtid = lane & 3;

    float acc[2][4][4];
    #pragma unroll
    for (int i = 0; i < 2; i++)
        #pragma unroll
        for (int j = 0; j < 4; j++)
            #pragma unroll
            for (int q = 0; q < 4; q++) acc[i][j][q] = 0.0f;

    fetchV(0);
    issueE(0, 0);
    stageV(0);
    asm volatile("cp.async.wait_group 0;" ::: "memory");
    __syncthreads();

    int buf = 0;
    for (int ch = 0; ch < nchunk; ch++) {
        if (ch + 1 < nchunk) {
            fetchV(ch + 1);
            issueE(ch + 1, buf ^ 1);
        }
        uint32_t eB = esb + (uint32_t)(buf * 32 * ES_STR * 2);
        uint32_t vB = vsb + (uint32_t)(buf * 32 * VS_STR * 2);
        #pragma unroll
        for (int ks = 0; ks < 2; ks++) {
            int kk = ks * 16;
            uint32_t af[2][4];
            #pragma unroll
            for (int mt = 0; mt < 2; mt++) {
                int tb = wm + mt * 16;
                int srow = kk + (grp >> 1) * 8 + lr;
                int tcol = tb + (grp & 1) * 8;
                ldsm4t(af[mt], eB + (uint32_t)(srow * ES_STR + tcol) * 2u);
            }
            uint32_t bf[4][2];
            #pragma unroll
            for (int ntp = 0; ntp < 2; ntp++) {
                int db = wn + ntp * 16;
                int srow = kk + (grp & 1) * 8 + lr;
                int dcol = db + (grp >> 1) * 8;
                uint32_t r4[4];
                ldsm4t(r4, vB + (uint32_t)(srow * VS_STR + dcol) * 2u);
                bf[2 * ntp][0] = r4[0]; bf[2 * ntp][1] = r4[1];
                bf[2 * ntp + 1][0] = r4[2]; bf[2 * ntp + 1][1] = r4[3];
            }
            #pragma unroll
            for (int mt = 0; mt < 2; mt++)
                #pragma unroll
                for (int nt = 0; nt < 4; nt++)
                    mma_f16(acc[mt][nt], af[mt], bf[nt]);
        }
        if (ch + 1 < nchunk) {
            stageV(buf ^ 1);
            asm volatile("cp.async.wait_group 0;" ::: "memory");
            __syncthreads();
            buf ^= 1;
        }
    }

    #pragma unroll
    for (int mt = 0; mt < 2; mt++)
        #pragma unroll
        for (int nt = 0; nt < 4; nt++)
            #pragma unroll
            for (int half = 0; half < 2; half++) {
                int t = t0 + wm + mt * 16 + half * 8 + qid;
                int d = wn + nt * 8 + 2 * qtid;
                *(uint32_t*)(attn + (size_t)(b * T + t) * CC + h * HS + d) =
                    packh2(acc[mt][nt][half * 2 + 0], acc[mt][nt][half * 2 + 1]);
            }
}

// ---------------- launch ----------------------------------------------------
extern "C" void kernel_launch(void* const* d_in, const int* in_sizes, int n_in,
                              void* d_out, int out_size) {
    (void)in_sizes; (void)n_in; (void)out_size;
    const float* x      = (const float*)d_in[0];
    const float* wq     = (const float*)d_in[1];
    const float* wk     = (const float*)d_in[2];
    const float* wv     = (const float*)d_in[3];
    const float* w_proj = (const float*)d_in[4];
    const float* b_proj = (const float*)d_in[5];
    const float* w1     = (const float*)d_in[6];
    const float* b1     = (const float*)d_in[7];
    const float* w2     = (const float*)d_in[8];
    const float* b2     = (const float*)d_in[9];
    const float* ln1_g  = (const float*)d_in[10];
    const float* ln1_b  = (const float*)d_in[11];
    const float* ln2_g  = (const float*)d_in[12];
    const float* ln2_b  = (const float*)d_in[13];
    float* out = (float*)d_out;

    void *ph, *pqkv, *pwei, *pzp, *pattn, *px1, *pu;
    void *pwqkv, *pwproj, *pw1, *pw2;
    cudaGetSymbolAddress(&ph,    g_h);
    cudaGetSymbolAddress(&pqkv,  g_qkv);
    cudaGetSymbolAddress(&pwei,  g_wei);
    cudaGetSymbolAddress(&pzp,   g_zpart);
    cudaGetSymbolAddress(&pattn, g_attn);
    cudaGetSymbolAddress(&px1,   g_x1);
    cudaGetSymbolAddress(&pu,    g_u);
    cudaGetSymbolAddress(&pwqkv, g_wqkvT);
    cudaGetSymbolAddress(&pwproj, g_wprojT);
    cudaGetSymbolAddress(&pw1,   g_w1T);
    cudaGetSymbolAddress(&pw2,   g_w2T);
    __half* fh     = (__half*)ph;
    __half* fqkv   = (__half*)pqkv;
    __half* fwei   = (__half*)pwei;
    float*  fzp    = (float*)pzp;
    __half* fattn  = (__half*)pattn;
    __half* fx1    = (__half*)px1;
    __half* fu     = (__half*)pu;
    __half* fwqkvT = (__half*)pwqkv;
    __half* fwprojT= (__half*)pwproj;
    __half* fw1T   = (__half*)pw1;
    __half* fw2T   = (__half*)pw2;

    const int SMEM_S  = 2 * 128 * 36 * 4;                            // 36864
    const int SMEM_AV = 2 * 32 * ES_STR * 2 + 2 * 32 * VS_STR * 2 + 1024; // 27648
    const int SMEM_G  = 3 * GS_STAGE * 4;                            // 110592
    cudaFuncSetAttribute(scores_tc, cudaFuncAttributeMaxDynamicSharedMemorySize, SMEM_S);
    cudaFuncSetAttribute(av_tc, cudaFuncAttributeMaxDynamicSharedMemorySize, SMEM_AV);
    cudaFuncSetAttribute(gemm_h<0, 1, 0>, cudaFuncAttributeMaxDynamicSharedMemorySize, SMEM_G);
    cudaFuncSetAttribute(gemm_h<1, 1, 0>, cudaFuncAttributeMaxDynamicSharedMemorySize, SMEM_G);
    cudaFuncSetAttribute(gemm_h<1, 0, 1>, cudaFuncAttributeMaxDynamicSharedMemorySize, SMEM_G);
    cudaFuncSetAttribute(gemm_h<2, 1, 0>, cudaFuncAttributeMaxDynamicSharedMemorySize, SMEM_G);

    // 0) weight prep (fp16, n-major) — single launch
    prep_all<<<1728, 256>>>(wq, wk, wv, w_proj, w1, w2,
                            fwqkvT, fwprojT, fw1T, fw2T);
    // 1) LN1 (fp32 in), 2 rows per block
    ln_kernel<float><<<BT / 2, 256>>>(x, ln1_g, ln1_b, fh);
    // 2) QKV projection (out fp16)
    gemm_h<0, 1, 0><<<dim3(QKVN / 128, BT / 128), 256, SMEM_G>>>(
        fh, fwqkvT, nullptr, nullptr, fqkv, BT, QKVN, CC);
    // 3) scores -> E = exp(sigma*S) masked (fp16), + row-sum partials
    scores_tc<<<dim3(3, NB * NH), 256, SMEM_S>>>(fqkv, fwei, fzp);
    // 4) O = E * (iz*V)  (fp16 out; iz computed in-kernel from zpart)
    av_tc<<<dim3(2, NB * NH), 256, SMEM_AV>>>(fqkv, fwei, fzp, fattn);
    // 5) x1 = x + attn @ w_proj + b_proj (fp16 out, fp32 residual)
    gemm_h<1, 1, 0><<<dim3(CC / 128, BT / 128), 256, SMEM_G>>>(
        fattn, fwprojT, b_proj, x, fx1, BT, CC, CC);
    // 6) LN2 (fp16 in), 2 rows per block
    ln_kernel<__half><<<BT / 2, 256>>>(fx1, ln2_g, ln2_b, fh);
    // 7) u = relu(h2 @ w1 + b1) (fp16 out)
    gemm_h<2, 1, 0><<<dim3(C4 / 128, BT / 128), 256, SMEM_G>>>(
        fh, fw1T, b1, nullptr, fu, BT, C4, CC);
    // 8) out = x1 + u @ w2 + b2 (fp32 out, fp16 residual)
    gemm_h<1, 0, 1><<<dim3(CC / 128, BT / 128), 256, SMEM_G>>>(
        fu, fw2T, b2, fx1, out, BT, CC, C4);
}

// round 16
// speedup vs baseline: 1.2495x; 1.0160x over previous
#include <cuda_runtime.h>
#include <cuda_fp16.h>
#include <cstddef>
#include <cstdint>

// Problem constants
#define NB   128          // batch
#define T    256          // sequence
#define CC   384          // embed
#define NH   6            // heads
#define HS   64           // head size
#define C4   1536         // 4*C
#define QKVN 1152         // 3*C
#define BT   32768        // NB*T

#define SCALE_ATT 0.05103103630798288f  // 384^-0.5

// ---------------- scratch (device globals; no allocation allowed) ----------
__device__ __half g_h[BT * CC];                      // LN output (fp16)
__device__ __half g_qkv[(size_t)BT * QKVN];          // q|k|v (fp16)
__device__ __half g_wei[(size_t)NB * NH * T * T];    // E^T[s][t] (fp16)
__device__ float  g_zpart[NB * NH * 4 * T];          // per-warp-column row sums
__device__ __half g_attn[BT * CC];                   // attention output (fp16)
__device__ __half g_x1[BT * CC];                     // residual stream (fp16)
__device__ __half g_u[(size_t)BT * C4];              // MLP hidden (fp16)
// n-major fp16 weights: Wt[n][k]
__device__ __half g_wqkvT[QKVN * CC];
__device__ __half g_wprojT[CC * CC];
__device__ __half g_w1T[(size_t)C4 * CC];
__device__ __half g_w2T[(size_t)CC * C4];

// ---------------- fused LN1 + weight prep (one launch) ----------------------
// blocks [0, BT/2): LN1 (2 rows each). blocks [BT/2, BT/2+1728): transposes.
__global__ void __launch_bounds__(256)
ln1_prep(const float* __restrict__ x, const float* __restrict__ g,
         const float* __restrict__ b, __half* __restrict__ out,
         const float* __restrict__ wq, const float* __restrict__ wk,
         const float* __restrict__ wv, const float* __restrict__ w_proj,
         const float* __restrict__ w1, const float* __restrict__ w2,
         __half* __restrict__ wqkvT, __half* __restrict__ wprojT,
         __half* __restrict__ w1T, __half* __restrict__ w2T) {
    if (blockIdx.x < BT / 2) {
        // ---- LN1, 2 rows per block ----
        int half = threadIdx.x >> 7;
        int t = threadIdx.x & 127;
        int row = blockIdx.x * 2 + half;
        const float* xr = x + (size_t)row * CC;
        float v0 = xr[t], v1 = xr[t + 128], v2 = xr[t + 256];
        float s  = v0 + v1 + v2;
        float ss = v0 * v0 + v1 * v1 + v2 * v2;
        __shared__ float red[2][4];
        __shared__ float red2[2][4];
        __shared__ float stat[2][2];
        #pragma unroll
        for (int o = 16; o > 0; o >>= 1) {
            s  += __shfl_down_sync(0xffffffffu, s, o);
            ss += __shfl_down_sync(0xffffffffu, ss, o);
        }
        int warp = t >> 5, lane = t & 31;
        if (lane == 0) { red[half][warp] = s; red2[half][warp] = ss; }
        __syncthreads();
        if (t == 0) {
            float S  = red[half][0] + red[half][1] + red[half][2] + red[half][3];
            float SS = red2[half][0] + red2[half][1] + red2[half][2] + red2[half][3];
            float mu = S * (1.0f / CC);
            float var = SS * (1.0f / CC) - mu * mu;
            stat[half][0] = mu;
            stat[half][1] = rsqrtf(var + 1e-5f);
        }
        __syncthreads();
        float mu = stat[half][0], inv = stat[half][1];
        __half* o = out + (size_t)row * CC;
        o[t]       = __float2half((v0 - mu) * inv * g[t]       + b[t]);
        o[t + 128] = __float2half((v1 - mu) * inv * g[t + 128] + b[t + 128]);
        o[t + 256] = __float2half((v2 - mu) * inv * g[t + 256] + b[t + 256]);
        return;
    }
    // ---- weight transposes ----
    __shared__ float tile[32][33];
    int bid = blockIdx.x - BT / 2;
    const float* src;
    __half* dst;
    int cols, dstLd, dstRowOff, tidx;
    if (bid < 432) {
        int j = bid / 24, t = bid % 24;
        int w = j / 6, h = j % 6;
        src = (w == 0 ? wq : w == 1 ? wk : wv) + (size_t)h * CC * HS;
        cols = HS; dst = wqkvT; dstLd = CC; dstRowOff = w * CC + h * HS;
        tidx = t;
    } else if (bid < 576) {
        src = w_proj; cols = CC; dst = wprojT; dstLd = CC; dstRowOff = 0;
        tidx = bid - 432;
    } else if (bid < 1152) {
        src = w1; cols = C4; dst = w1T; dstLd = CC; dstRowOff = 0;
        tidx = bid - 576;
    } else {
        src = w2; cols = CC; dst = w2T; dstLd = C4; dstRowOff = 0;
        tidx = bid - 1152;
    }
    int c32 = cols >> 5;
    int n0 = (tidx % c32) * 32;
    int k0 = (tidx / c32) * 32;
    int tx = threadIdx.x & 31, ty = threadIdx.x >> 5;
    #pragma unroll
    for (int i = 0; i < 32; i += 8)
        tile[ty + i][tx] = src[(size_t)(k0 + ty + i) * cols + n0 + tx];
    __syncthreads();
    #pragma unroll
    for (int i = 0; i < 32; i += 8)
        dst[(size_t)(dstRowOff + n0 + ty + i) * dstLd + k0 + tx] =
            __float2half(tile[tx][ty + i]);
}

// ---------------- LayerNorm (LN2): 2 rows per 256-thread block --------------
template <typename Tin>
__global__ void __launch_bounds__(256)
ln_kernel(const Tin* __restrict__ x, const float* __restrict__ g,
          const float* __restrict__ b, __half* __restrict__ out) {
    int half = threadIdx.x >> 7;
    int t = threadIdx.x & 127;
    int row = blockIdx.x * 2 + half;
    const Tin* xr = x + (size_t)row * CC;
    float v0 = (float)xr[t], v1 = (float)xr[t + 128], v2 = (float)xr[t + 256];
    float s  = v0 + v1 + v2;
    float ss = v0 * v0 + v1 * v1 + v2 * v2;
    __shared__ float red[2][4];
    __shared__ float red2[2][4];
    __shared__ float stat[2][2];
    #pragma unroll
    for (int o = 16; o > 0; o >>= 1) {
        s  += __shfl_down_sync(0xffffffffu, s, o);
        ss += __shfl_down_sync(0xffffffffu, ss, o);
    }
    int warp = t >> 5, lane = t & 31;
    if (lane == 0) { red[half][warp] = s; red2[half][warp] = ss; }
    __syncthreads();
    if (t == 0) {
        float S  = red[half][0] + red[half][1] + red[half][2] + red[half][3];
        float SS = red2[half][0] + red2[half][1] + red2[half][2] + red2[half][3];
        float mu = S * (1.0f / CC);
        float var = SS * (1.0f / CC) - mu * mu;
        stat[half][0] = mu;
        stat[half][1] = rsqrtf(var + 1e-5f);
    }
    __syncthreads();
    float mu = stat[half][0], inv = stat[half][1];
    __half* o = out + (size_t)row * CC;
    o[t]       = __float2half((v0 - mu) * inv * g[t]       + b[t]);
    o[t + 128] = __float2half((v1 - mu) * inv * g[t + 128] + b[t + 128]);
    o[t + 256] = __float2half((v2 - mu) * inv * g[t + 256] + b[t + 256]);
}

// ---------------- helpers -----------------------------------------------------
__device__ __forceinline__ uint32_t packh2(float lo, float hi) {
    __half2 h = __floats2half2_rn(lo, hi);
    return *(uint32_t*)&h;
}
__device__ __forceinline__ uint32_t smem_u32(const void* p) {
    uint32_t a;
    asm("{ .reg .u64 t; cvta.to.shared.u64 t, %1; cvt.u32.u64 %0, t; }"
        : "=r"(a) : "l"(p));
    return a;
}

__device__ __forceinline__ void mma_f16(float* d, const uint32_t* a, const uint32_t* b) {
    asm volatile(
        "mma.sync.aligned.m16n8k16.row.col.f32.f16.f16.f32 "
        "{%0,%1,%2,%3}, {%4,%5,%6,%7}, {%8,%9}, {%0,%1,%2,%3};"
        : "+f"(d[0]), "+f"(d[1]), "+f"(d[2]), "+f"(d[3])
        : "r"(a[0]), "r"(a[1]), "r"(a[2]), "r"(a[3]), "r"(b[0]), "r"(b[1]));
}

__device__ __forceinline__ void ldsm4t(uint32_t* r, uint32_t a) {
    asm volatile(
        "ldmatrix.sync.aligned.m8n8.x4.trans.shared.b16 {%0,%1,%2,%3}, [%4];"
        : "=r"(r[0]), "=r"(r[1]), "=r"(r[2]), "=r"(r[3]) : "r"(a));
}

// exp(x) for |x| <= ~1; degree-7 Taylor, pure FMA pipe.
__device__ __forceinline__ float exp_poly(float x) {
    float r = fmaf(x, 1.0f / 5040.0f, 1.0f / 720.0f);
    r = fmaf(x, r, 1.0f / 120.0f);
    r = fmaf(x, r, 1.0f / 24.0f);
    r = fmaf(x, r, 1.0f / 6.0f);
    r = fmaf(x, r, 0.5f);
    r = fmaf(x, r, 1.0f);
    r = fmaf(x, r, 1.0f);
    return r;
}

// ---------------- fp16 tensor-core GEMM, BK=64, 3-stage cp.async -------------
#define GS_STR 36                     // u32 stride per row (64 halves + pad)
#define GS_TILE (128 * GS_STR)        // u32 per matrix per stage (4608)
#define GS_STAGE (2 * GS_TILE)        // u32 per stage (A+B)
template <int EPI, int OUTH, int RESH>
__global__ void __launch_bounds__(256, 2)
gemm_h(const __half* __restrict__ A, const __half* __restrict__ Bt,
       const float* __restrict__ bias, const void* __restrict__ res,
       void* __restrict__ CoutV, int M, int N, int K) {
    extern __shared__ char gsm[];
    uint32_t* Ssm = (uint32_t*)gsm;

    int tid  = threadIdx.x;
    int m0   = blockIdx.y * 128;
    int n0   = blockIdx.x * 128;
    int warp = tid >> 5, lane = tid & 31;
    int wm = (warp >> 1) * 32;
    int wn = (warp & 1) * 64;
    int qid  = lane >> 2;
    int qtid = lane & 3;

    float acc[2][8][4];
    #pragma unroll
    for (int i = 0; i < 2; i++)
        #pragma unroll
        for (int j = 0; j < 8; j++)
            #pragma unroll
            for (int q = 0; q < 4; q++) acc[i][j][q] = 0.0f;

    uint32_t sbase = smem_u32(gsm);
    int KT = K >> 6;

    auto issue = [&](int kt, int buf) {
        uint32_t stg = sbase + (uint32_t)(buf * GS_STAGE) * 4u;
        #pragma unroll
        for (int i = 0; i < 4; i++) {
            int idx = tid + 256 * i;
            int r = idx >> 3, seg = idx & 7;
            uint32_t da = stg + (uint32_t)(r * GS_STR * 4 + seg * 16);
            uint32_t db = da + (uint32_t)(GS_TILE * 4);
            const __half* pa = A  + (size_t)(m0 + r) * K + kt * 64 + seg * 8;
            const __half* pb = Bt + (size_t)(n0 + r) * K + kt * 64 + seg * 8;
            asm volatile(
                "cp.async.cg.shared.global [%0], [%1], 16;\n\t"
                "cp.async.cg.shared.global [%2], [%3], 16;"
                :: "r"(da), "l"(pa), "r"(db), "l"(pb) : "memory");
        }
        asm volatile("cp.async.commit_group;" ::: "memory");
    };

    issue(0, 0);
    if (KT > 1) issue(1, 1);

    int buf = 0;
    for (int kt = 0; kt < KT; kt++) {
        if (kt + 1 < KT)
            asm volatile("cp.async.wait_group 1;" ::: "memory");
        else
            asm volatile("cp.async.wait_group 0;" ::: "memory");
        __syncthreads();
        if (kt + 2 < KT) {
            int nb = buf + 2; if (nb >= 3) nb -= 3;
            issue(kt + 2, nb);
        }
        const uint32_t* As = Ssm + buf * GS_STAGE;
        const uint32_t* Bs = As + GS_TILE;
        #pragma unroll
        for (int ks = 0; ks < 4; ks++) {
            int kk = ks * 8;
            uint32_t af[2][4], bf[8][2];
            #pragma unroll
            for (int mt = 0; mt < 2; mt++) {
                int r = wm + mt * 16 + qid;
                af[mt][0] = As[r * GS_STR + kk + qtid];
                af[mt][1] = As[(r + 8) * GS_STR + kk + qtid];
                af[mt][2] = As[r * GS_STR + kk + qtid + 4];
                af[mt][3] = As[(r + 8) * GS_STR + kk + qtid + 4];
            }
            #pragma unroll
            for (int nt = 0; nt < 8; nt++) {
                int c = wn + nt * 8 + qid;
                bf[nt][0] = Bs[c * GS_STR + kk + qtid];
                bf[nt][1] = Bs[c * GS_STR + kk + qtid + 4];
            }
            #pragma unroll
            for (int mt = 0; mt < 2; mt++)
                #pragma unroll
                for (int nt = 0; nt < 8; nt++)
                    mma_f16(acc[mt][nt], af[mt], bf[nt]);
        }
        if (++buf == 3) buf = 0;
    }

    #pragma unroll
    for (int mt = 0; mt < 2; mt++) {
        #pragma unroll
        for (int nt = 0; nt < 8; nt++) {
            int r = m0 + wm + mt * 16 + qid;
            int c = n0 + wn + nt * 8 + 2 * qtid;
            #pragma unroll
            for (int half = 0; half < 2; half++) {
                int rr = r + half * 8;
                float2 v;
                v.x = acc[mt][nt][half * 2 + 0];
                v.y = acc[mt][nt][half * 2 + 1];
                if (EPI == 1) {
                    float2 bb = *(const float2*)(bias + c);
                    float2 rf;
                    if (RESH) {
                        uint32_t ru = *(const uint32_t*)((const __half*)res + (size_t)rr * N + c);
                        rf = __half22float2(*(__half2*)&ru);
                    } else {
                        rf = *(const float2*)((const float*)res + (size_t)rr * N + c);
                    }
                    v.x += bb.x + rf.x; v.y += bb.y + rf.y;
                } else if (EPI == 2) {
                    float2 bb = *(const float2*)(bias + c);
                    v.x = fmaxf(v.x + bb.x, 0.0f);
                    v.y = fmaxf(v.y + bb.y, 0.0f);
                }
                if (OUTH) {
                    __half* Co = (__half*)CoutV;
                    *(uint32_t*)(Co + (size_t)rr * N + c) = packh2(v.x, v.y);
                } else {
                    float* Co = (float*)CoutV;
                    *(float2*)(Co + (size_t)rr * N + c) = v;
                }
            }
        }
    }
}

// ---------------- scores: E^T[s][t] = mask ? exp(sigma*K[s].Q[t]) : 0 -------
// cp.async staging; narrow bf live range; 3 CTAs/SM target.
__global__ void __launch_bounds__(256, 3)
scores_tc(const __half* __restrict__ qkv, __half* __restrict__ wei,
          float* __restrict__ zpart) {
    extern __shared__ uint32_t ssm[];
    uint32_t* Ks = ssm;                // [128][36] half2
    uint32_t* Qs = ssm + 128 * 36;

    int bh = blockIdx.y;
    int b = bh / NH, h = bh % NH;
    int qidx = blockIdx.x;
    int sq = (qidx == 2) ? 1 : 0;
    int tq = (qidx == 0) ? 0 : 1;
    int s0 = sq * 128, t0 = tq * 128;
    int tid = threadIdx.x;

    uint32_t ksb = smem_u32(Ks);
    uint32_t qsb = smem_u32(Qs);
    #pragma unroll
    for (int i = 0; i < 4; i++) {
        int idx = tid + 256 * i;
        int r = idx >> 3, u4 = idx & 7;
        uint32_t dk = ksb + (uint32_t)((r * 36 + u4 * 4) * 4);
        uint32_t dq = qsb + (uint32_t)((r * 36 + u4 * 4) * 4);
        const __half* bk = qkv + (size_t)(b * T + s0 + r) * QKVN + CC + h * HS + u4 * 8;
        const __half* bq = qkv + (size_t)(b * T + t0 + r) * QKVN + h * HS + u4 * 8;
        asm volatile(
            "cp.async.cg.shared.global [%0], [%1], 16;\n\t"
            "cp.async.cg.shared.global [%2], [%3], 16;"
            :: "r"(dk), "l"(bk), "r"(dq), "l"(bq) : "memory");
    }
    asm volatile("cp.async.commit_group;\n\tcp.async.wait_group 0;" ::: "memory");
    __syncthreads();

    int warp = tid >> 5, lane = tid & 31;
    int qid = lane >> 2, qtid = lane & 3;
    int wm = (warp >> 1) * 32;          // s offset in tile
    int wn = (warp & 1) * 64;           // t offset in tile

    float acc[2][8][4];
    #pragma unroll
    for (int i = 0; i < 2; i++)
        #pragma unroll
        for (int j = 0; j < 8; j++)
            #pragma unroll
            for (int q = 0; q < 4; q++) acc[i][j][q] = 0.0f;

    #pragma unroll
    for (int ks = 0; ks < 4; ks++) {
        int kk = ks * 8;
        uint32_t af[2][4];
        #pragma unroll
        for (int mt = 0; mt < 2; mt++) {
            int r = wm + mt * 16 + qid;
            af[mt][0] = Ks[r * 36 + kk + qtid];
            af[mt][1] = Ks[(r + 8) * 36 + kk + qtid];
            af[mt][2] = Ks[r * 36 + kk + qtid + 4];
            af[mt][3] = Ks[(r + 8) * 36 + kk + qtid + 4];
        }
        #pragma unroll
        for (int nt = 0; nt < 8; nt++) {
            int c = wn + nt * 8 + qid;
            uint32_t bb[2];
            bb[0] = Qs[c * 36 + kk + qtid];
            bb[1] = Qs[c * 36 + kk + qtid + 4];
            mma_f16(acc[0][nt], af[0], bb);
            mma_f16(acc[1][nt], af[1], bb);
        }
    }

    __half* W = wei + (size_t)bh * (T * T);
    float rsum[2][2] = {{0.0f, 0.0f}, {0.0f, 0.0f}};

    #pragma unroll
    for (int mt = 0; mt < 2; mt++)
        #pragma unroll
        for (int half = 0; half < 2; half++) {
            int s = s0 + wm + mt * 16 + half * 8 + qid;
            #pragma unroll
            for (int nt = 0; nt < 8; nt++) {
                int tb = t0 + wn + nt * 8 + 2 * qtid;
                float e0 = 0.0f, e1 = 0.0f;
                if (tb + 0 >= s) e0 = exp_poly(acc[mt][nt][half * 2 + 0] * SCALE_ATT);
                if (tb + 1 >= s) e1 = exp_poly(acc[mt][nt][half * 2 + 1] * SCALE_ATT);
                rsum[mt][half] += e0 + e1;
                *(uint32_t*)(W + (size_t)s * T + tb) = packh2(e0, e1);
            }
        }

    int tcol = tq * 2 + (warp & 1);
    #pragma unroll
    for (int mt = 0; mt < 2; mt++)
        #pragma unroll
        for (int half = 0; half < 2; half++) {
            float v = rsum[mt][half];
            v += __shfl_xor_sync(0xffffffffu, v, 1);
            v += __shfl_xor_sync(0xffffffffu, v, 2);
            if (qtid == 0) {
                int s = s0 + wm + mt * 16 + half * 8 + qid;
                zpart[(bh * 4 + tcol) * T + s] = v;
            }
        }
}

// ---------------- av: O[t][d] = sum_s E^T[s][t] * (iz[s]*V[s][d]) -----------
#define ES_STR 136
#define VS_STR 72
__global__ void __launch_bounds__(256, 3)
av_tc(const __half* __restrict__ qkv, const __half* __restrict__ wei,
      const float* __restrict__ zp, __half* __restrict__ attn) {
    extern __shared__ char avsm[];
    __half* Vs = (__half*)(avsm + 2 * 32 * ES_STR * 2);
    float* izs = (float*)(avsm + 2 * 32 * ES_STR * 2 + 2 * 32 * VS_STR * 2);

    int bh = blockIdx.y;
    int b = bh / NH, h = bh % NH;
    int t0 = blockIdx.x * 128;
    int tid = threadIdx.x;
    int lane = tid & 31, warp = tid >> 5;

    {
        const float* p = zp + bh * 4 * T;
        int s = tid;
        float z = p[2 * T + s] + p[3 * T + s];
        if (s < 128) z += p[s] + p[T + s];
        izs[s] = 1.0f / z;
    }
    __syncthreads();

    const __half* W  = wei + (size_t)bh * (T * T);
    const __half* Vg = qkv + (size_t)(b * T) * QKVN + 2 * CC + h * HS;
    int nchunk = (t0 == 0) ? 4 : 8;

    uint32_t esb = smem_u32(avsm);
    uint32_t vsb = smem_u32(Vs);

    int vr = tid >> 3, vdc = (tid & 7) * 8;

    auto issueE = [&](int ch, int buf) {
        #pragma unroll
        for (int i = 0; i < 2; i++) {
            int idx = tid + 256 * i;
            int r = idx >> 4, seg = idx & 15;
            uint32_t dst = esb + (uint32_t)(buf * 32 * ES_STR * 2 + r * ES_STR * 2 + seg * 16);
            const __half* src = W + (size_t)(ch * 32 + r) * T + t0 + seg * 8;
            asm volatile("cp.async.cg.shared.global [%0], [%1], 16;"
                         :: "r"(dst), "l"(src) : "memory");
        }
        asm volatile("cp.async.commit_group;" ::: "memory");
    };
    uint4 vreg;
    float izr;
    auto fetchV = [&](int ch) {
        vreg = *(const uint4*)(Vg + (size_t)(ch * 32 + vr) * QKVN + vdc);
        izr = izs[ch * 32 + vr];
    };
    auto stageV = [&](int buf) {
        __half2 hiz = __float2half2_rn(izr);
        __half2* hv = (__half2*)&vreg;
        uint4 o;
        __half2* ho = (__half2*)&o;
        ho[0] = __hmul2(hv[0], hiz);
        ho[1] = __hmul2(hv[1], hiz);
        ho[2] = __hmul2(hv[2], hiz);
        ho[3] = __hmul2(hv[3], hiz);
        *(uint4*)(Vs + buf * 32 * VS_STR + vr * VS_STR + vdc) = o;
    };

    int wm = (warp >> 1) * 32;
    int wn = (warp & 1) * 32;
    int grp = lane >> 3, lr = lane & 7;
    int qid = lane >> 2, qtid = lane & 3;

    float acc[2][4][4];
    #pragma unroll
    for (int i = 0; i < 2; i++)
        #pragma unroll
        for (int j = 0; j < 4; j++)
            #pragma unroll
            for (int q = 0; q < 4; q++) acc[i][j][q] = 0.0f;

    fetchV(0);
    issueE(0, 0);
    stageV(0);
    asm volatile("cp.async.wait_group 0;" ::: "memory");
    __syncthreads();

    int buf = 0;
    for (int ch = 0; ch < nchunk; ch++) {
        if (ch + 1 < nchunk) {
            fetchV(ch + 1);
            issueE(ch + 1, buf ^ 1);
        }
        uint32_t eB = esb + (uint32_t)(buf * 32 * ES_STR * 2);
        uint32_t vB = vsb + (uint32_t)(buf * 32 * VS_STR * 2);
        #pragma unroll
        for (int ks = 0; ks < 2; ks++) {
            int kk = ks * 16;
            uint32_t af[2][4];
            #pragma unroll
            for (int mt = 0; mt < 2; mt++) {
                int tb = wm + mt * 16;
                int srow = kk + (grp >> 1) * 8 + lr;
                int tcol = tb + (grp & 1) * 8;
                ldsm4t(af[mt], eB + (uint32_t)(srow * ES_STR + tcol) * 2u);
            }
            uint32_t bf[4][2];
            #pragma unroll
            for (int ntp = 0; ntp < 2; ntp++) {
                int db = wn + ntp * 16;
                int srow = kk + (grp & 1) * 8 + lr;
                int dcol = db + (grp >> 1) * 8;
                uint32_t r4[4];
                ldsm4t(r4, vB + (uint32_t)(srow * VS_STR + dcol) * 2u);
                bf[2 * ntp][0] = r4[0]; bf[2 * ntp][1] = r4[1];
                bf[2 * ntp + 1][0] = r4[2]; bf[2 * ntp + 1][1] = r4[3];
            }
            #pragma unroll
            for (int mt = 0; mt < 2; mt++)
                #pragma unroll
                for (int nt = 0; nt < 4; nt++)
                    mma_f16(acc[mt][nt], af[mt], bf[nt]);
        }
        if (ch + 1 < nchunk) {
            stageV(buf ^ 1);
            asm volatile("cp.async.wait_group 0;" ::: "memory");
            __syncthreads();
            buf ^= 1;
        }
    }

    #pragma unroll
    for (int mt = 0; mt < 2; mt++)
        #pragma unroll
        for (int nt = 0; nt < 4; nt++)
            #pragma unroll
            for (int half = 0; half < 2; half++) {
                int t = t0 + wm + mt * 16 + half * 8 + qid;
                int d = wn + nt * 8 + 2 * qtid;
                *(uint32_t*)(attn + (size_t)(b * T + t) * CC + h * HS + d) =
                    packh2(acc[mt][nt][half * 2 + 0], acc[mt][nt][half * 2 + 1]);
            }
}

// ---------------- launch ----------------------------------------------------
extern "C" void kernel_launch(void* const* d_in, const int* in_sizes, int n_in,
                              void* d_out, int out_size) {
    (void)in_sizes; (void)n_in; (void)out_size;
    const float* x      = (const float*)d_in[0];
    const float* wq     = (const float*)d_in[1];
    const float* wk     = (const float*)d_in[2];
    const float* wv     = (const float*)d_in[3];
    const float* w_proj = (const float*)d_in[4];
    const float* b_proj = (const float*)d_in[5];
    const float* w1     = (const float*)d_in[6];
    const float* b1     = (const float*)d_in[7];
    const float* w2     = (const float*)d_in[8];
    const float* b2     = (const float*)d_in[9];
    const float* ln1_g  = (const float*)d_in[10];
    const float* ln1_b  = (const float*)d_in[11];
    const float* ln2_g  = (const float*)d_in[12];
    const float* ln2_b  = (const float*)d_in[13];
    float* out = (float*)d_out;

    void *ph, *pqkv, *pwei, *pzp, *pattn, *px1, *pu;
    void *pwqkv, *pwproj, *pw1, *pw2;
    cudaGetSymbolAddress(&ph,    g_h);
    cudaGetSymbolAddress(&pqkv,  g_qkv);
    cudaGetSymbolAddress(&pwei,  g_wei);
    cudaGetSymbolAddress(&pzp,   g_zpart);
    cudaGetSymbolAddress(&pattn, g_attn);
    cudaGetSymbolAddress(&px1,   g_x1);
    cudaGetSymbolAddress(&pu,    g_u);
    cudaGetSymbolAddress(&pwqkv, g_wqkvT);
    cudaGetSymbolAddress(&pwproj, g_wprojT);
    cudaGetSymbolAddress(&pw1,   g_w1T);
    cudaGetSymbolAddress(&pw2,   g_w2T);
    __half* fh     = (__half*)ph;
    __half* fqkv   = (__half*)pqkv;
    __half* fwei   = (__half*)pwei;
    float*  fzp    = (float*)pzp;
    __half* fattn  = (__half*)pattn;
    __half* fx1    = (__half*)px1;
    __half* fu     = (__half*)pu;
    __half* fwqkvT = (__half*)pwqkv;
    __half* fwprojT= (__half*)pwproj;
    __half* fw1T   = (__half*)pw1;
    __half* fw2T   = (__half*)pw2;

    const int SMEM_S  = 2 * 128 * 36 * 4;                            // 36864
    const int SMEM_AV = 2 * 32 * ES_STR * 2 + 2 * 32 * VS_STR * 2 + 1024; // 27648
    const int SMEM_G  = 3 * GS_STAGE * 4;                            // 110592
    cudaFuncSetAttribute(scores_tc, cudaFuncAttributeMaxDynamicSharedMemorySize, SMEM_S);
    cudaFuncSetAttribute(av_tc, cudaFuncAttributeMaxDynamicSharedMemorySize, SMEM_AV);
    cudaFuncSetAttribute(gemm_h<0, 1, 0>, cudaFuncAttributeMaxDynamicSharedMemorySize, SMEM_G);
    cudaFuncSetAttribute(gemm_h<1, 1, 0>, cudaFuncAttributeMaxDynamicSharedMemorySize, SMEM_G);
    cudaFuncSetAttribute(gemm_h<1, 0, 1>, cudaFuncAttributeMaxDynamicSharedMemorySize, SMEM_G);
    cudaFuncSetAttribute(gemm_h<2, 1, 0>, cudaFuncAttributeMaxDynamicSharedMemorySize, SMEM_G);

    // 0+1) fused weight prep + LN1 (one launch)
    ln1_prep<<<BT / 2 + 1728, 256>>>(x, ln1_g, ln1_b, fh,
                                     wq, wk, wv, w_proj, w1, w2,
                                     fwqkvT, fwprojT, fw1T, fw2T);
    // 2) QKV projection (out fp16)
    gemm_h<0, 1, 0><<<dim3(QKVN / 128, BT / 128), 256, SMEM_G>>>(
        fh, fwqkvT, nullptr, nullptr, fqkv, BT, QKVN, CC);
    // 3) scores -> E = exp(sigma*S) masked (fp16), + row-sum partials
    scores_tc<<<dim3(3, NB * NH), 256, SMEM_S>>>(fqkv, fwei, fzp);
    // 4) O = E * (iz*V)  (fp16 out; iz computed in-kernel from zpart)
    av_tc<<<dim3(2, NB * NH), 256, SMEM_AV>>>(fqkv, fwei, fzp, fattn);
    // 5) x1 = x + attn @ w_proj + b_proj (fp16 out, fp32 residual)
    gemm_h<1, 1, 0><<<dim3(CC / 128, BT / 128), 256, SMEM_G>>>(
        fattn, fwprojT, b_proj, x, fx1, BT, CC, CC);
    // 6) LN2 (fp16 in), 2 rows per block
    ln_kernel<__half><<<BT / 2, 256>>>(fx1, ln2_g, ln2_b, fh);
    // 7) u = relu(h2 @ w1 + b1) (fp16 out)
    gemm_h<2, 1, 0><<<dim3(C4 / 128, BT / 128), 256, SMEM_G>>>(
        fh, fw1T, b1, nullptr, fu, BT, C4, CC);
    // 8) out = x1 + u @ w2 + b2 (fp32 out, fp16 residual)
    gemm_h<1, 0, 1><<<dim3(CC / 128, BT / 128), 256, SMEM_G>>>(
        fu, fw2T, b2, fx1, out, BT, CC, C4);
}

// round 17
// speedup vs baseline: 1.2547x; 1.0042x over previous
#include <cuda_runtime.h>
#include <cuda_fp16.h>
#include <cstddef>
#include <cstdint>

// Problem constants
#define NB   128          // batch
#define T    256          // sequence
#define CC   384          // embed
#define NH   6            // heads
#define HS   64           // head size
#define C4   1536         // 4*C
#define QKVN 1152         // 3*C
#define BT   32768        // NB*T

#define SCALE_ATT 0.05103103630798288f  // 384^-0.5

// ---------------- scratch (device globals; no allocation allowed) ----------
__device__ __half g_h[BT * CC];                      // LN output (fp16)
__device__ __half g_qkv[(size_t)BT * QKVN];          // q|k|v (fp16)
__device__ __half g_wei[(size_t)NB * NH * T * T];    // E^T[s][t] (fp16)
__device__ float  g_zpart[NB * NH * 4 * T];          // per-warp-column row sums
__device__ __half g_attn[BT * CC];                   // attention output (fp16)
__device__ __half g_x1[BT * CC];                     // residual stream (fp16)
__device__ __half g_u[(size_t)BT * C4];              // MLP hidden (fp16)
// n-major fp16 weights: Wt[n][k]
__device__ __half g_wqkvT[QKVN * CC];
__device__ __half g_wprojT[CC * CC];
__device__ __half g_w1T[(size_t)C4 * CC];
__device__ __half g_w2T[(size_t)CC * C4];

// ---------------- fused LN1 + weight prep (one launch) ----------------------
__global__ void __launch_bounds__(256)
ln1_prep(const float* __restrict__ x, const float* __restrict__ g,
         const float* __restrict__ b, __half* __restrict__ out,
         const float* __restrict__ wq, const float* __restrict__ wk,
         const float* __restrict__ wv, const float* __restrict__ w_proj,
         const float* __restrict__ w1, const float* __restrict__ w2,
         __half* __restrict__ wqkvT, __half* __restrict__ wprojT,
         __half* __restrict__ w1T, __half* __restrict__ w2T) {
    if (blockIdx.x < BT / 2) {
        int half = threadIdx.x >> 7;
        int t = threadIdx.x & 127;
        int row = blockIdx.x * 2 + half;
        const float* xr = x + (size_t)row * CC;
        float v0 = xr[t], v1 = xr[t + 128], v2 = xr[t + 256];
        float s  = v0 + v1 + v2;
        float ss = v0 * v0 + v1 * v1 + v2 * v2;
        __shared__ float red[2][4];
        __shared__ float red2[2][4];
        __shared__ float stat[2][2];
        #pragma unroll
        for (int o = 16; o > 0; o >>= 1) {
            s  += __shfl_down_sync(0xffffffffu, s, o);
            ss += __shfl_down_sync(0xffffffffu, ss, o);
        }
        int warp = t >> 5, lane = t & 31;
        if (lane == 0) { red[half][warp] = s; red2[half][warp] = ss; }
        __syncthreads();
        if (t == 0) {
            float S  = red[half][0] + red[half][1] + red[half][2] + red[half][3];
            float SS = red2[half][0] + red2[half][1] + red2[half][2] + red2[half][3];
            float mu = S * (1.0f / CC);
            float var = SS * (1.0f / CC) - mu * mu;
            stat[half][0] = mu;
            stat[half][1] = rsqrtf(var + 1e-5f);
        }
        __syncthreads();
        float mu = stat[half][0], inv = stat[half][1];
        __half* o = out + (size_t)row * CC;
        o[t]       = __float2half((v0 - mu) * inv * g[t]       + b[t]);
        o[t + 128] = __float2half((v1 - mu) * inv * g[t + 128] + b[t + 128]);
        o[t + 256] = __float2half((v2 - mu) * inv * g[t + 256] + b[t + 256]);
        return;
    }
    __shared__ float tile[32][33];
    int bid = blockIdx.x - BT / 2;
    const float* src;
    __half* dst;
    int cols, dstLd, dstRowOff, tidx;
    if (bid < 432) {
        int j = bid / 24, t = bid % 24;
        int w = j / 6, h = j % 6;
        src = (w == 0 ? wq : w == 1 ? wk : wv) + (size_t)h * CC * HS;
        cols = HS; dst = wqkvT; dstLd = CC; dstRowOff = w * CC + h * HS;
        tidx = t;
    } else if (bid < 576) {
        src = w_proj; cols = CC; dst = wprojT; dstLd = CC; dstRowOff = 0;
        tidx = bid - 432;
    } else if (bid < 1152) {
        src = w1; cols = C4; dst = w1T; dstLd = CC; dstRowOff = 0;
        tidx = bid - 576;
    } else {
        src = w2; cols = CC; dst = w2T; dstLd = C4; dstRowOff = 0;
        tidx = bid - 1152;
    }
    int c32 = cols >> 5;
    int n0 = (tidx % c32) * 32;
    int k0 = (tidx / c32) * 32;
    int tx = threadIdx.x & 31, ty = threadIdx.x >> 5;
    #pragma unroll
    for (int i = 0; i < 32; i += 8)
        tile[ty + i][tx] = src[(size_t)(k0 + ty + i) * cols + n0 + tx];
    __syncthreads();
    #pragma unroll
    for (int i = 0; i < 32; i += 8)
        dst[(size_t)(dstRowOff + n0 + ty + i) * dstLd + k0 + tx] =
            __float2half(tile[tx][ty + i]);
}

// ---------------- LayerNorm (LN2): 2 rows per 256-thread block --------------
template <typename Tin>
__global__ void __launch_bounds__(256)
ln_kernel(const Tin* __restrict__ x, const float* __restrict__ g,
          const float* __restrict__ b, __half* __restrict__ out) {
    int half = threadIdx.x >> 7;
    int t = threadIdx.x & 127;
    int row = blockIdx.x * 2 + half;
    const Tin* xr = x + (size_t)row * CC;
    float v0 = (float)xr[t], v1 = (float)xr[t + 128], v2 = (float)xr[t + 256];
    float s  = v0 + v1 + v2;
    float ss = v0 * v0 + v1 * v1 + v2 * v2;
    __shared__ float red[2][4];
    __shared__ float red2[2][4];
    __shared__ float stat[2][2];
    #pragma unroll
    for (int o = 16; o > 0; o >>= 1) {
        s  += __shfl_down_sync(0xffffffffu, s, o);
        ss += __shfl_down_sync(0xffffffffu, ss, o);
    }
    int warp = t >> 5, lane = t & 31;
    if (lane == 0) { red[half][warp] = s; red2[half][warp] = ss; }
    __syncthreads();
    if (t == 0) {
        float S  = red[half][0] + red[half][1] + red[half][2] + red[half][3];
        float SS = red2[half][0] + red2[half][1] + red2[half][2] + red2[half][3];
        float mu = S * (1.0f / CC);
        float var = SS * (1.0f / CC) - mu * mu;
        stat[half][0] = mu;
        stat[half][1] = rsqrtf(var + 1e-5f);
    }
    __syncthreads();
    float mu = stat[half][0], inv = stat[half][1];
    __half* o = out + (size_t)row * CC;
    o[t]       = __float2half((v0 - mu) * inv * g[t]       + b[t]);
    o[t + 128] = __float2half((v1 - mu) * inv * g[t + 128] + b[t + 128]);
    o[t + 256] = __float2half((v2 - mu) * inv * g[t + 256] + b[t + 256]);
}

// ---------------- helpers -----------------------------------------------------
__device__ __forceinline__ uint32_t packh2(float lo, float hi) {
    __half2 h = __floats2half2_rn(lo, hi);
    return *(uint32_t*)&h;
}
__device__ __forceinline__ uint32_t smem_u32(const void* p) {
    uint32_t a;
    asm("{ .reg .u64 t; cvta.to.shared.u64 t, %1; cvt.u32.u64 %0, t; }"
        : "=r"(a) : "l"(p));
    return a;
}

__device__ __forceinline__ void mma_f16(float* d, const uint32_t* a, const uint32_t* b) {
    asm volatile(
        "mma.sync.aligned.m16n8k16.row.col.f32.f16.f16.f32 "
        "{%0,%1,%2,%3}, {%4,%5,%6,%7}, {%8,%9}, {%0,%1,%2,%3};"
        : "+f"(d[0]), "+f"(d[1]), "+f"(d[2]), "+f"(d[3])
        : "r"(a[0]), "r"(a[1]), "r"(a[2]), "r"(a[3]), "r"(b[0]), "r"(b[1]));
}

__device__ __forceinline__ void ldsm4t(uint32_t* r, uint32_t a) {
    asm volatile(
        "ldmatrix.sync.aligned.m8n8.x4.trans.shared.b16 {%0,%1,%2,%3}, [%4];"
        : "=r"(r[0]), "=r"(r[1]), "=r"(r[2]), "=r"(r[3]) : "r"(a));
}

// exp(x) for |x| <= ~1; degree-7 Taylor, pure FMA pipe.
__device__ __forceinline__ float exp_poly(float x) {
    float r = fmaf(x, 1.0f / 5040.0f, 1.0f / 720.0f);
    r = fmaf(x, r, 1.0f / 120.0f);
    r = fmaf(x, r, 1.0f / 24.0f);
    r = fmaf(x, r, 1.0f / 6.0f);
    r = fmaf(x, r, 0.5f);
    r = fmaf(x, r, 1.0f);
    r = fmaf(x, r, 1.0f);
    return r;
}

// ---------------- fp16 tensor-core GEMM, BK=64, 3-stage cp.async -------------
#define GS_STR 36                     // u32 stride per row (64 halves + pad)
#define GS_TILE (128 * GS_STR)        // u32 per matrix per stage (4608)
#define GS_STAGE (2 * GS_TILE)        // u32 per stage (A+B)
template <int EPI, int OUTH, int RESH>
__global__ void __launch_bounds__(256, 2)
gemm_h(const __half* __restrict__ A, const __half* __restrict__ Bt,
       const float* __restrict__ bias, const void* __restrict__ res,
       void* __restrict__ CoutV, int M, int N, int K) {
    extern __shared__ char gsm[];
    uint32_t* Ssm = (uint32_t*)gsm;

    int tid  = threadIdx.x;
    int m0   = blockIdx.y * 128;
    int n0   = blockIdx.x * 128;
    int warp = tid >> 5, lane = tid & 31;
    int wm = (warp >> 1) * 32;
    int wn = (warp & 1) * 64;
    int qid  = lane >> 2;
    int qtid = lane & 3;

    float acc[2][8][4];
    #pragma unroll
    for (int i = 0; i < 2; i++)
        #pragma unroll
        for (int j = 0; j < 8; j++)
            #pragma unroll
            for (int q = 0; q < 4; q++) acc[i][j][q] = 0.0f;

    uint32_t sbase = smem_u32(gsm);
    int KT = K >> 6;

    auto issue = [&](int kt, int buf) {
        uint32_t stg = sbase + (uint32_t)(buf * GS_STAGE) * 4u;
        #pragma unroll
        for (int i = 0; i < 4; i++) {
            int idx = tid + 256 * i;
            int r = idx >> 3, seg = idx & 7;
            uint32_t da = stg + (uint32_t)(r * GS_STR * 4 + seg * 16);
            uint32_t db = da + (uint32_t)(GS_TILE * 4);
            const __half* pa = A  + (size_t)(m0 + r) * K + kt * 64 + seg * 8;
            const __half* pb = Bt + (size_t)(n0 + r) * K + kt * 64 + seg * 8;
            asm volatile(
                "cp.async.cg.shared.global [%0], [%1], 16;\n\t"
                "cp.async.cg.shared.global [%2], [%3], 16;"
                :: "r"(da), "l"(pa), "r"(db), "l"(pb) : "memory");
        }
        asm volatile("cp.async.commit_group;" ::: "memory");
    };

    issue(0, 0);
    if (KT > 1) issue(1, 1);

    int buf = 0;
    for (int kt = 0; kt < KT; kt++) {
        if (kt + 1 < KT)
            asm volatile("cp.async.wait_group 1;" ::: "memory");
        else
            asm volatile("cp.async.wait_group 0;" ::: "memory");
        __syncthreads();
        if (kt + 2 < KT) {
            int nb = buf + 2; if (nb >= 3) nb -= 3;
            issue(kt + 2, nb);
        }
        const uint32_t* As = Ssm + buf * GS_STAGE;
        const uint32_t* Bs = As + GS_TILE;
        #pragma unroll
        for (int ks = 0; ks < 4; ks++) {
            int kk = ks * 8;
            uint32_t af[2][4], bf[8][2];
            #pragma unroll
            for (int mt = 0; mt < 2; mt++) {
                int r = wm + mt * 16 + qid;
                af[mt][0] = As[r * GS_STR + kk + qtid];
                af[mt][1] = As[(r + 8) * GS_STR + kk + qtid];
                af[mt][2] = As[r * GS_STR + kk + qtid + 4];
                af[mt][3] = As[(r + 8) * GS_STR + kk + qtid + 4];
            }
            #pragma unroll
            for (int nt = 0; nt < 8; nt++) {
                int c = wn + nt * 8 + qid;
                bf[nt][0] = Bs[c * GS_STR + kk + qtid];
                bf[nt][1] = Bs[c * GS_STR + kk + qtid + 4];
            }
            #pragma unroll
            for (int mt = 0; mt < 2; mt++)
                #pragma unroll
                for (int nt = 0; nt < 8; nt++)
                    mma_f16(acc[mt][nt], af[mt], bf[nt]);
        }
        if (++buf == 3) buf = 0;
    }

    #pragma unroll
    for (int mt = 0; mt < 2; mt++) {
        #pragma unroll
        for (int nt = 0; nt < 8; nt++) {
            int r = m0 + wm + mt * 16 + qid;
            int c = n0 + wn + nt * 8 + 2 * qtid;
            #pragma unroll
            for (int half = 0; half < 2; half++) {
                int rr = r + half * 8;
                float2 v;
                v.x = acc[mt][nt][half * 2 + 0];
                v.y = acc[mt][nt][half * 2 + 1];
                if (EPI == 1) {
                    float2 bb = *(const float2*)(bias + c);
                    float2 rf;
                    if (RESH) {
                        uint32_t ru = *(const uint32_t*)((const __half*)res + (size_t)rr * N + c);
                        rf = __half22float2(*(__half2*)&ru);
                    } else {
                        rf = *(const float2*)((const float*)res + (size_t)rr * N + c);
                    }
                    v.x += bb.x + rf.x; v.y += bb.y + rf.y;
                } else if (EPI == 2) {
                    float2 bb = *(const float2*)(bias + c);
                    v.x = fmaxf(v.x + bb.x, 0.0f);
                    v.y = fmaxf(v.y + bb.y, 0.0f);
                }
                if (OUTH) {
                    __half* Co = (__half*)CoutV;
                    *(uint32_t*)(Co + (size_t)rr * N + c) = packh2(v.x, v.y);
                } else {
                    float* Co = (float*)CoutV;
                    *(float2*)(Co + (size_t)rr * N + c) = v;
                }
            }
        }
    }
}

// ---------------- scores: E^T[s][t] = mask ? exp(sigma*K[s].Q[t]) : 0 -------
__global__ void __launch_bounds__(256, 3)
scores_tc(const __half* __restrict__ qkv, __half* __restrict__ wei,
          float* __restrict__ zpart) {
    extern __shared__ uint32_t ssm[];
    uint32_t* Ks = ssm;                // [128][36] half2
    uint32_t* Qs = ssm + 128 * 36;

    int bh = blockIdx.y;
    int b = bh / NH, h = bh % NH;
    int qidx = blockIdx.x;
    int sq = (qidx == 2) ? 1 : 0;
    int tq = (qidx == 0) ? 0 : 1;
    int s0 = sq * 128, t0 = tq * 128;
    int tid = threadIdx.x;

    uint32_t ksb = smem_u32(Ks);
    uint32_t qsb = smem_u32(Qs);
    #pragma unroll
    for (int i = 0; i < 4; i++) {
        int idx = tid + 256 * i;
        int r = idx >> 3, u4 = idx & 7;
        uint32_t dk = ksb + (uint32_t)((r * 36 + u4 * 4) * 4);
        uint32_t dq = qsb + (uint32_t)((r * 36 + u4 * 4) * 4);
        const __half* bk = qkv + (size_t)(b * T + s0 + r) * QKVN + CC + h * HS + u4 * 8;
        const __half* bq = qkv + (size_t)(b * T + t0 + r) * QKVN + h * HS + u4 * 8;
        asm volatile(
            "cp.async.cg.shared.global [%0], [%1], 16;\n\t"
            "cp.async.cg.shared.global [%2], [%3], 16;"
            :: "r"(dk), "l"(bk), "r"(dq), "l"(bq) : "memory");
    }
    asm volatile("cp.async.commit_group;\n\tcp.async.wait_group 0;" ::: "memory");
    __syncthreads();

    int warp = tid >> 5, lane = tid & 31;
    int qid = lane >> 2, qtid = lane & 3;
    int wm = (warp >> 1) * 32;          // s offset in tile
    int wn = (warp & 1) * 64;           // t offset in tile

    float acc[2][8][4];
    #pragma unroll
    for (int i = 0; i < 2; i++)
        #pragma unroll
        for (int j = 0; j < 8; j++)
            #pragma unroll
            for (int q = 0; q < 4; q++) acc[i][j][q] = 0.0f;

    #pragma unroll
    for (int ks = 0; ks < 4; ks++) {
        int kk = ks * 8;
        uint32_t af[2][4];
        #pragma unroll
        for (int mt = 0; mt < 2; mt++) {
            int r = wm + mt * 16 + qid;
            af[mt][0] = Ks[r * 36 + kk + qtid];
            af[mt][1] = Ks[(r + 8) * 36 + kk + qtid];
            af[mt][2] = Ks[r * 36 + kk + qtid + 4];
            af[mt][3] = Ks[(r + 8) * 36 + kk + qtid + 4];
        }
        #pragma unroll
        for (int nt = 0; nt < 8; nt++) {
            int c = wn + nt * 8 + qid;
            uint32_t bb[2];
            bb[0] = Qs[c * 36 + kk + qtid];
            bb[1] = Qs[c * 36 + kk + qtid + 4];
            mma_f16(acc[0][nt], af[0], bb);
            mma_f16(acc[1][nt], af[1], bb);
        }
    }

    __half* W = wei + (size_t)bh * (T * T);
    float rsum[2][2] = {{0.0f, 0.0f}, {0.0f, 0.0f}};

    #pragma unroll
    for (int mt = 0; mt < 2; mt++)
        #pragma unroll
        for (int half = 0; half < 2; half++) {
            int s = s0 + wm + mt * 16 + half * 8 + qid;
            #pragma unroll
            for (int nt = 0; nt < 8; nt++) {
                int tb = t0 + wn + nt * 8 + 2 * qtid;
                float e0 = 0.0f, e1 = 0.0f;
                if (tb + 0 >= s) e0 = exp_poly(acc[mt][nt][half * 2 + 0] * SCALE_ATT);
                if (tb + 1 >= s) e1 = exp_poly(acc[mt][nt][half * 2 + 1] * SCALE_ATT);
                rsum[mt][half] += e0 + e1;
                *(uint32_t*)(W + (size_t)s * T + tb) = packh2(e0, e1);
            }
        }

    int tcol = tq * 2 + (warp & 1);
    #pragma unroll
    for (int mt = 0; mt < 2; mt++)
        #pragma unroll
        for (int half = 0; half < 2; half++) {
            float v = rsum[mt][half];
            v += __shfl_xor_sync(0xffffffffu, v, 1);
            v += __shfl_xor_sync(0xffffffffu, v, 2);
            if (qtid == 0) {
                int s = s0 + wm + mt * 16 + half * 8 + qid;
                zpart[(bh * 4 + tcol) * T + s] = v;
            }
        }
}

// ---------------- av: O[t][d] = sum_s E^T[s][t] * (iz[s]*V[s][d]) -----------
// 3 E buffers w/ 2-chunk prefetch (wait_group 1); V double-buffered.
#define ES_STR 136
#define VS_STR 72
#define E_BUF (32 * ES_STR)   // halves per E buffer
#define V_BUF (32 * VS_STR)   // halves per V buffer
__global__ void __launch_bounds__(256, 3)
av_tc(const __half* __restrict__ qkv, const __half* __restrict__ wei,
      const float* __restrict__ zp, __half* __restrict__ attn) {
    extern __shared__ char avsm[];
    __half* Vs = (__half*)(avsm + 3 * E_BUF * 2);
    float* izs = (float*)(avsm + 3 * E_BUF * 2 + 2 * V_BUF * 2);

    int bh = blockIdx.y;
    int b = bh / NH, h = bh % NH;
    int t0 = blockIdx.x * 128;
    int tid = threadIdx.x;
    int lane = tid & 31, warp = tid >> 5;

    {
        const float* p = zp + bh * 4 * T;
        int s = tid;
        float z = p[2 * T + s] + p[3 * T + s];
        if (s < 128) z += p[s] + p[T + s];
        izs[s] = 1.0f / z;
    }
    __syncthreads();

    const __half* W  = wei + (size_t)bh * (T * T);
    const __half* Vg = qkv + (size_t)(b * T) * QKVN + 2 * CC + h * HS;
    int nchunk = (t0 == 0) ? 4 : 8;     // always >= 4

    uint32_t esb = smem_u32(avsm);
    uint32_t vsb = smem_u32(Vs);

    int vr = tid >> 3, vdc = (tid & 7) * 8;

    auto issueE = [&](int ch, int buf) {
        #pragma unroll
        for (int i = 0; i < 2; i++) {
            int idx = tid + 256 * i;
            int r = idx >> 4, seg = idx & 15;
            uint32_t dst = esb + (uint32_t)(buf * E_BUF * 2 + r * ES_STR * 2 + seg * 16);
            const __half* src = W + (size_t)(ch * 32 + r) * T + t0 + seg * 8;
            asm volatile("cp.async.cg.shared.global [%0], [%1], 16;"
                         :: "r"(dst), "l"(src) : "memory");
        }
        asm volatile("cp.async.commit_group;" ::: "memory");
    };
    uint4 vreg;
    float izr;
    auto fetchV = [&](int ch) {
        vreg = *(const uint4*)(Vg + (size_t)(ch * 32 + vr) * QKVN + vdc);
        izr = izs[ch * 32 + vr];
    };
    auto stageV = [&](int buf) {
        __half2 hiz = __float2half2_rn(izr);
        __half2* hv = (__half2*)&vreg;
        uint4 o;
        __half2* ho = (__half2*)&o;
        ho[0] = __hmul2(hv[0], hiz);
        ho[1] = __hmul2(hv[1], hiz);
        ho[2] = __hmul2(hv[2], hiz);
        ho[3] = __hmul2(hv[3], hiz);
        *(uint4*)(Vs + buf * V_BUF + vr * VS_STR + vdc) = o;
    };

    int wm = (warp >> 1) * 32;
    int wn = (warp & 1) * 32;
    int grp = lane >> 3, lr = lane & 7;
    int qid = lane >> 2, qtid = lane & 3;

    float acc[2][4][4];
    #pragma unroll
    for (int i = 0; i < 2; i++)
        #pragma unroll
        for (int j = 0; j < 4; j++)
            #pragma unroll
            for (int q = 0; q < 4; q++) acc[i][j][q] = 0.0f;

    // prologue: issue E0 and E1, stage V0; wait for E0 only (E1 in flight)
    issueE(0, 0);
    issueE(1, 1);
    fetchV(0);
    stageV(0);
    asm volatile("cp.async.wait_group 1;" ::: "memory");
    __syncthreads();

    int ebuf = 0;
    for (int ch = 0; ch < nchunk; ch++) {
        if (ch + 2 < nchunk) {
            int nb = ebuf + 2; if (nb >= 3) nb -= 3;
            issueE(ch + 2, nb);
        }
        if (ch + 1 < nchunk) fetchV(ch + 1);

        uint32_t eB = esb + (uint32_t)(ebuf * E_BUF * 2);
        uint32_t vB = vsb + (uint32_t)((ch & 1) * V_BUF * 2);
        #pragma unroll
        for (int ks = 0; ks < 2; ks++) {
            int kk = ks * 16;
            uint32_t af[2][4];
            #pragma unroll
            for (int mt = 0; mt < 2; mt++) {
                int tb = wm + mt * 16;
                int srow = kk + (grp >> 1) * 8 + lr;
                int tcol = tb + (grp & 1) * 8;
                ldsm4t(af[mt], eB + (uint32_t)(srow * ES_STR + tcol) * 2u);
            }
            uint32_t bf[4][2];
            #pragma unroll
            for (int ntp = 0; ntp < 2; ntp++) {
                int db = wn + ntp * 16;
                int srow = kk + (grp & 1) * 8 + lr;
                int dcol = db + (grp >> 1) * 8;
                uint32_t r4[4];
                ldsm4t(r4, vB + (uint32_t)(srow * VS_STR + dcol) * 2u);
                bf[2 * ntp][0] = r4[0]; bf[2 * ntp][1] = r4[1];
                bf[2 * ntp + 1][0] = r4[2]; bf[2 * ntp + 1][1] = r4[3];
            }
            #pragma unroll
            for (int mt = 0; mt < 2; mt++)
                #pragma unroll
                for (int nt = 0; nt < 4; nt++)
                    mma_f16(acc[mt][nt], af[mt], bf[nt]);
        }

        if (ch + 1 < nchunk) {
            stageV((ch + 1) & 1);
            // wait so that E[ch+1] is complete; E[ch+2] (if issued) may remain
            if (ch + 2 < nchunk)
                asm volatile("cp.async.wait_group 1;" ::: "memory");
            else
                asm volatile("cp.async.wait_group 0;" ::: "memory");
            __syncthreads();
            if (++ebuf == 3) ebuf = 0;
        }
    }

    #pragma unroll
    for (int mt = 0; mt < 2; mt++)
        #pragma unroll
        for (int nt = 0; nt < 4; nt++)
            #pragma unroll
            for (int half = 0; half < 2; half++) {
                int t = t0 + wm + mt * 16 + half * 8 + qid;
                int d = wn + nt * 8 + 2 * qtid;
                *(uint32_t*)(attn + (size_t)(b * T + t) * CC + h * HS + d) =
                    packh2(acc[mt][nt][half * 2 + 0], acc[mt][nt][half * 2 + 1]);
            }
}

// ---------------- launch ----------------------------------------------------
extern "C" void kernel_launch(void* const* d_in, const int* in_sizes, int n_in,
                              void* d_out, int out_size) {
    (void)in_sizes; (void)n_in; (void)out_size;
    const float* x      = (const float*)d_in[0];
    const float* wq     = (const float*)d_in[1];
    const float* wk     = (const float*)d_in[2];
    const float* wv     = (const float*)d_in[3];
    const float* w_proj = (const float*)d_in[4];
    const float* b_proj = (const float*)d_in[5];
    const float* w1     = (const float*)d_in[6];
    const float* b1     = (const float*)d_in[7];
    const float* w2     = (const float*)d_in[8];
    const float* b2     = (const float*)d_in[9];
    const float* ln1_g  = (const float*)d_in[10];
    const float* ln1_b  = (const float*)d_in[11];
    const float* ln2_g  = (const float*)d_in[12];
    const float* ln2_b  = (const float*)d_in[13];
    float* out = (float*)d_out;

    void *ph, *pqkv, *pwei, *pzp, *pattn, *px1, *pu;
    void *pwqkv, *pwproj, *pw1, *pw2;
    cudaGetSymbolAddress(&ph,    g_h);
    cudaGetSymbolAddress(&pqkv,  g_qkv);
    cudaGetSymbolAddress(&pwei,  g_wei);
    cudaGetSymbolAddress(&pzp,   g_zpart);
    cudaGetSymbolAddress(&pattn, g_attn);
    cudaGetSymbolAddress(&px1,   g_x1);
    cudaGetSymbolAddress(&pu,    g_u);
    cudaGetSymbolAddress(&pwqkv, g_wqkvT);
    cudaGetSymbolAddress(&pwproj, g_wprojT);
    cudaGetSymbolAddress(&pw1,   g_w1T);
    cudaGetSymbolAddress(&pw2,   g_w2T);
    __half* fh     = (__half*)ph;
    __half* fqkv   = (__half*)pqkv;
    __half* fwei   = (__half*)pwei;
    float*  fzp    = (float*)pzp;
    __half* fattn  = (__half*)pattn;
    __half* fx1    = (__half*)px1;
    __half* fu     = (__half*)pu;
    __half* fwqkvT = (__half*)pwqkv;
    __half* fwprojT= (__half*)pwproj;
    __half* fw1T   = (__half*)pw1;
    __half* fw2T   = (__half*)pw2;

    const int SMEM_S  = 2 * 128 * 36 * 4;                            // 36864
    const int SMEM_AV = 3 * E_BUF * 2 + 2 * V_BUF * 2 + 1024;        // 36352
    const int SMEM_G  = 3 * GS_STAGE * 4;                            // 110592
    cudaFuncSetAttribute(scores_tc, cudaFuncAttributeMaxDynamicSharedMemorySize, SMEM_S);
    cudaFuncSetAttribute(av_tc, cudaFuncAttributeMaxDynamicSharedMemorySize, SMEM_AV);
    cudaFuncSetAttribute(gemm_h<0, 1, 0>, cudaFuncAttributeMaxDynamicSharedMemorySize, SMEM_G);
    cudaFuncSetAttribute(gemm_h<1, 1, 0>, cudaFuncAttributeMaxDynamicSharedMemorySize, SMEM_G);
    cudaFuncSetAttribute(gemm_h<1, 0, 1>, cudaFuncAttributeMaxDynamicSharedMemorySize, SMEM_G);
    cudaFuncSetAttribute(gemm_h<2, 1, 0>, cudaFuncAttributeMaxDynamicSharedMemorySize, SMEM_G);

    // 0+1) fused weight prep + LN1 (one launch)
    ln1_prep<<<BT / 2 + 1728, 256>>>(x, ln1_g, ln1_b, fh,
                                     wq, wk, wv, w_proj, w1, w2,
                                     fwqkvT, fwprojT, fw1T, fw2T);
    // 2) QKV projection (out fp16)
    gemm_h<0, 1, 0><<<dim3(QKVN / 128, BT / 128), 256, SMEM_G>>>(
        fh, fwqkvT, nullptr, nullptr, fqkv, BT, QKVN, CC);
    // 3) scores -> E = exp(sigma*S) masked (fp16), + row-sum partials
    scores_tc<<<dim3(3, NB * NH), 256, SMEM_S>>>(fqkv, fwei, fzp);
    // 4) O = E * (iz*V)  (fp16 out; iz computed in-kernel from zpart)
    av_tc<<<dim3(2, NB * NH), 256, SMEM_AV>>>(fqkv, fwei, fzp, fattn);
    // 5) x1 = x + attn @ w_proj + b_proj (fp16 out, fp32 residual)
    gemm_h<1, 1, 0><<<dim3(CC / 128, BT / 128), 256, SMEM_G>>>(
        fattn, fwprojT, b_proj, x, fx1, BT, CC, CC);
    // 6) LN2 (fp16 in), 2 rows per block
    ln_kernel<__half><<<BT / 2, 256>>>(fx1, ln2_g, ln2_b, fh);
    // 7) u = relu(h2 @ w1 + b1) (fp16 out)
    gemm_h<2, 1, 0><<<dim3(C4 / 128, BT / 128), 256, SMEM_G>>>(
        fh, fw1T, b1, nullptr, fu, BT, C4, CC);
    // 8) out = x1 + u @ w2 + b2 (fp32 out, fp16 residual)
    gemm_h<1, 0, 1><<<dim3(CC / 128, BT / 128), 256, SMEM_G>>>(
        fu, fw2T, b2, fx1, out, BT, CC, C4);
}